// round 9
// baseline (speedup 1.0000x reference)
#include <cuda_runtime.h>
#include <cuda_bf16.h>
#include <cuda_fp16.h>
#include <cstdint>

#define NN   100000
#define DD   128
#define EE   800000
#define NET  2
#define TM   64
#define LN_EPS 1e-5f

#define XS 136          // fp16 row stride (272B -> conflict-free ldmatrix)
#define LODELTA 17408   // XH -> XL plane delta (64*136*2)

// ---- smem byte offsets (110,592 B total -> 2 CTAs/SM) ----
#define OFF_XH 0
#define OFF_XL 17408        // X lo for GEMM1; then K stage; then V stage (fp16)
#define OFF_W0 34816
#define OFF_W1 69632
#define OFF_SC 104448       // 64*16 fp32 = 4KB
#define OFF_BI 108544       // 512 fp32 = 2KB
#define SMEM_BYTES 110592

// ---- scratch (device globals) ----
__device__ __nv_bfloat16 g_Whb[(size_t)NET * NN * DD];   // bf16 messages
__device__ __half g_Wsplit[NET * 4 * DD * DD];           // fp16 weights [e][mat][128][128]
__device__ int g_cnt[NET * NN];
__device__ int g_off[NET * NN + 1];
__device__ int g_cur[NET * NN];
__device__ int g_bsum[256];
__device__ int g_sorted[NET * EE];

// ---- warp MMA primitives ----
__device__ __forceinline__ void ldmat4(uint32_t* r, uint32_t addr) {
    asm volatile("ldmatrix.sync.aligned.m8n8.x4.shared.b16 {%0,%1,%2,%3}, [%4];"
        : "=r"(r[0]), "=r"(r[1]), "=r"(r[2]), "=r"(r[3]) : "r"(addr));
}
__device__ __forceinline__ void ldmat4t(uint32_t* r, uint32_t addr) {
    asm volatile("ldmatrix.sync.aligned.m8n8.x4.trans.shared.b16 {%0,%1,%2,%3}, [%4];"
        : "=r"(r[0]), "=r"(r[1]), "=r"(r[2]), "=r"(r[3]) : "r"(addr));
}
__device__ __forceinline__ void mma16816(float* c, const uint32_t* a, const uint32_t* b) {
    asm volatile("mma.sync.aligned.m16n8k16.row.col.f32.f16.f16.f32 "
        "{%0,%1,%2,%3}, {%4,%5,%6,%7}, {%8,%9}, {%0,%1,%2,%3};"
        : "+f"(c[0]), "+f"(c[1]), "+f"(c[2]), "+f"(c[3])
        : "r"(a[0]), "r"(a[1]), "r"(a[2]), "r"(a[3]), "r"(b[0]), "r"(b[1]));
}
#define CP_COMMIT() asm volatile("cp.async.commit_group;" ::: "memory")
#define CP_WAIT(n)  asm volatile("cp.async.wait_group %0;" :: "n"(n) : "memory")

__device__ __forceinline__ void split2h(float a, float b, uint32_t& hi, uint32_t& lo) {
    __half ha = __float2half_rn(a), hb = __float2half_rn(b);
    __half la = __float2half_rn(a - __half2float(ha));
    __half lb = __float2half_rn(b - __half2float(hb));
    __half2 h; h.x = ha; h.y = hb;
    __half2 l; l.x = la; l.y = lb;
    hi = *(uint32_t*)&h; lo = *(uint32_t*)&l;
}

// cp.async one 32KB fp16 weight matrix (128 rows) into XS-strided smem
__device__ __forceinline__ void cpw(uint32_t sb, int offW, const __half* __restrict__ gsrc, int t) {
#pragma unroll
    for (int i = 0; i < 8; i++) {
        int u = i * 256 + t;
        int k = u >> 4, n16 = u & 15;
        uint32_t dh = sb + offW + k * (XS * 2) + n16 * 16;
        const char* gh = (const char*)gsrc + k * 256 + n16 * 16;
        asm volatile("cp.async.cg.shared.global [%0], [%1], 16;" :: "r"(dh), "l"(gh));
    }
}

// fp16 GEMM, warp tile M16 x N64: ALO -> (Xh + Xl)*Wh ; else Xh*Wh
// warp w: mt = w>>1 (M-tile of 16 rows), nh = w&1 (N half of 64 cols)
template<bool ALO>
__device__ __forceinline__ void wgemm(char* smem, float acc[8][4], int offW, int mt, int nh, int lane) {
    const int r = lane & 7, sel = lane >> 3;
    const int rowoff = (sel & 1) ? 8 : 0;
    const int coloff = (sel & 2) ? 8 : 0;
    const uint32_t sb = (uint32_t)__cvta_generic_to_shared(smem);
    const int arow = mt * 16 + r + rowoff;
    const uint32_t axh = sb + OFF_XH + (uint32_t)(arow * XS + coloff) * 2;
#pragma unroll
    for (int kk = 0; kk < 8; kk++) {
        uint32_t Ah[4], Al[4];
        ldmat4(Ah, axh + kk * 32);
        if (ALO) ldmat4(Al, axh + LODELTA + kk * 32);
        const int brow = kk * 16 + r + rowoff;
        const uint32_t bh = sb + offW + (uint32_t)(brow * XS + nh * 64 + coloff) * 2;
#pragma unroll
        for (int nt16 = 0; nt16 < 4; nt16++) {
            uint32_t Bh[4];
            ldmat4t(Bh, bh + nt16 * 32);
            mma16816(acc[2 * nt16],     Ah, Bh);
            mma16816(acc[2 * nt16 + 1], Ah, Bh + 2);
            if (ALO) {
                mma16816(acc[2 * nt16],     Al, Bh);
                mma16816(acc[2 * nt16 + 1], Al, Bh + 2);
            }
        }
    }
}

__device__ __forceinline__ void zacc(float acc[8][4]) {
#pragma unroll
    for (int i = 0; i < 8; i++) { acc[i][0] = acc[i][1] = acc[i][2] = acc[i][3] = 0.f; }
}

// ---- pre-convert weights: fp32 -> fp16 ----
__global__ void wsplit_kernel(const float* __restrict__ Wt, const float* __restrict__ Kw,
                              const float* __restrict__ Qw, const float* __restrict__ Vw) {
    int i = blockIdx.x * 256 + threadIdx.x;
    int mat = i >> 14, j = i & 16383;
    int e = blockIdx.y;
    const float* srcs[4] = {Wt, Kw, Qw, Vw};
    float v = srcs[mat][(size_t)e * 16384 + j];
    g_Wsplit[(size_t)(e * 4 + mat) * 16384 + j] = __float2half_rn(v);
}

// ================= fused transform (TM=64, 2 CTAs/SM) =================
__global__ void __launch_bounds__(256, 2) transform_kernel(
    const float* __restrict__ feat,
    const float* __restrict__ bt, const float* __restrict__ Kb,
    const float* __restrict__ Qb, const float* __restrict__ Vb)
{
    extern __shared__ char smem[];
    const uint32_t sb = (uint32_t)__cvta_generic_to_shared(smem);
    const int e    = blockIdx.y;
    const int base = blockIdx.x * TM;
    const int t    = threadIdx.x;
    const int w = t >> 5, lane = t & 31;
    const int mt = w >> 1, nh = w & 1;
    const int g = lane >> 2, c = lane & 3;
    const int R0 = mt * 16 + g, R1 = R0 + 8;
    float* sScf = (float*)(smem + OFF_SC);
    float* sBI  = (float*)(smem + OFF_BI);
    const __half* Wb = g_Wsplit + (size_t)e * 4 * 16384;

    cpw(sb, OFF_W0, Wb,         t); CP_COMMIT();   // Wt
    cpw(sb, OFF_W1, Wb + 16384, t); CP_COMMIT();   // Kw

    if (t < 128) {
        sBI[t]       = bt[e * DD + t];
        sBI[128 + t] = Kb[e * DD + t];
        sBI[256 + t] = Qb[e * DD + t];
        sBI[384 + t] = Vb[e * DD + t];
    }

    // feat -> X (fp16 hi/lo): 64 rows x 128 cols, 8 float4 per thread
#pragma unroll
    for (int i = 0; i < 8; i++) {
        int u = i * 256 + t;
        int m = u >> 5, k = (u & 31) * 4;
        int node = base + m;
        float4 v = make_float4(0.f, 0.f, 0.f, 0.f);
        if (node < NN) v = *(const float4*)(feat + (size_t)node * DD + k);
        uint32_t h0, l0, h1, l1;
        split2h(v.x, v.y, h0, l0);
        split2h(v.z, v.w, h1, l1);
        *(uint2*)(smem + OFF_XH + ((size_t)m * XS + k) * 2) = make_uint2(h0, h1);
        *(uint2*)(smem + OFF_XL + ((size_t)m * XS + k) * 2) = make_uint2(l0, l1);
    }
    CP_WAIT(1);
    __syncthreads();

    float acc[8][4];

    // ---- GEMM1: Wh0 = feat @ Wt ((Xh+Xl)*Wh) ----
    zacc(acc);
    wgemm<true>(smem, acc, OFF_W0, mt, nh, lane);
    __syncthreads();

    // Wh0 + bt -> XH (XL becomes free)
#pragma unroll
    for (int nt = 0; nt < 8; nt++) {
        int col = nh * 64 + nt * 8 + 2 * c;
        float bx = sBI[col], by = sBI[col + 1];
        __half2 p0 = __floats2half2_rn(acc[nt][0] + bx, acc[nt][1] + by);
        __half2 p1 = __floats2half2_rn(acc[nt][2] + bx, acc[nt][3] + by);
        *(uint32_t*)(smem + OFF_XH + ((size_t)R0 * XS + col) * 2) = *(uint32_t*)&p0;
        *(uint32_t*)(smem + OFF_XH + ((size_t)R1 * XS + col) * 2) = *(uint32_t*)&p1;
    }
    cpw(sb, OFF_W0, Wb + 2 * 16384, t); CP_COMMIT();   // Qw
    CP_WAIT(1);                                        // Kw ready
    __syncthreads();

    // ---- GEMM2: K (hi-only) ----
    zacc(acc);
    wgemm<false>(smem, acc, OFF_W1, mt, nh, lane);
    __syncthreads();

    // stage K (+Kb) -> XL fp16
#pragma unroll
    for (int nt = 0; nt < 8; nt++) {
        int col = nh * 64 + nt * 8 + 2 * c;
        float bx = sBI[128 + col], by = sBI[128 + col + 1];
        __half2 p0 = __floats2half2_rn(acc[nt][0] + bx, acc[nt][1] + by);
        __half2 p1 = __floats2half2_rn(acc[nt][2] + bx, acc[nt][3] + by);
        *(uint32_t*)(smem + OFF_XL + ((size_t)R0 * XS + col) * 2) = *(uint32_t*)&p0;
        *(uint32_t*)(smem + OFF_XL + ((size_t)R1 * XS + col) * 2) = *(uint32_t*)&p1;
    }
    CP_WAIT(0);                                        // Qw ready
    __syncthreads();

    cpw(sb, OFF_W1, Wb + 3 * 16384, t); CP_COMMIT();   // Vw (overlaps Q GEMM + scores)

    // ---- GEMM3: Q (hi-only) ----
    zacc(acc);
    wgemm<false>(smem, acc, OFF_W0, mt, nh, lane);
#pragma unroll
    for (int nt = 0; nt < 8; nt++) {
        int col = nh * 64 + nt * 8 + 2 * c;
        float bx = sBI[256 + col], by = sBI[256 + col + 1];
        acc[nt][0] += bx; acc[nt][1] += by;
        acc[nt][2] += bx; acc[nt][3] += by;
    }

    // ---- scores: warp (mt,nh) computes heads 2nh, 2nh+1 for its rows ----
    const float scale = 0.17677669529663687f;
#pragma unroll
    for (int g2 = 0; g2 < 4; g2++) {
        float2 kv0[4], kv1[4];
#pragma unroll
        for (int j = 0; j < 4; j++) {
            __half2 k0 = *(const __half2*)(smem + OFF_XL + ((size_t)R0 * XS + g2 * 32 + j * 8 + 2 * c) * 2);
            __half2 k1 = *(const __half2*)(smem + OFF_XL + ((size_t)R1 * XS + g2 * 32 + j * 8 + 2 * c) * 2);
            kv0[j] = __half22float2(k0);
            kv1[j] = __half22float2(k1);
        }
#pragma unroll
        for (int hl = 0; hl < 2; hl++) {
            int h = 2 * nh + hl;
            float p0 = 0.f, p1 = 0.f;
#pragma unroll
            for (int j = 0; j < 4; j++) {
                p0 += acc[hl * 4 + j][0] * kv0[j].x + acc[hl * 4 + j][1] * kv0[j].y;
                p1 += acc[hl * 4 + j][2] * kv1[j].x + acc[hl * 4 + j][3] * kv1[j].y;
            }
            p0 += __shfl_xor_sync(0xffffffffu, p0, 1);
            p0 += __shfl_xor_sync(0xffffffffu, p0, 2);
            p1 += __shfl_xor_sync(0xffffffffu, p1, 1);
            p1 += __shfl_xor_sync(0xffffffffu, p1, 2);
            if (c == 0) {
                sScf[R0 * 16 + h * 4 + g2] = p0 * scale;
                sScf[R1 * 16 + h * 4 + g2] = p1 * scale;
            }
        }
    }
    __syncthreads();

    // ---- softmax: 64 rows x 4 heads = 256 pairs, one per thread ----
    {
        int row = t >> 2, h = t & 3;
        float4 s = *(float4*)(sScf + row * 16 + h * 4);
        float m = fmaxf(fmaxf(s.x, s.y), fmaxf(s.z, s.w));
        float e0 = __expf(s.x - m), e1 = __expf(s.y - m), e2 = __expf(s.z - m), e3 = __expf(s.w - m);
        float inv = 1.f / (e0 + e1 + e2 + e3);
        *(float4*)(sScf + row * 16 + h * 4) = make_float4(e0 * inv, e1 * inv, e2 * inv, e3 * inv);
    }
    CP_WAIT(0);                                        // Vw ready
    __syncthreads();

    // ---- GEMM4: V (hi-only) ----
    zacc(acc);
    wgemm<false>(smem, acc, OFF_W1, mt, nh, lane);

    // stage V (+Vb) -> XL fp16 (K no longer needed)
    __syncthreads();                                   // all K reads (scores) done
#pragma unroll
    for (int nt = 0; nt < 8; nt++) {
        int col = nh * 64 + nt * 8 + 2 * c;
        float bx = sBI[384 + col], by = sBI[384 + col + 1];
        __half2 p0 = __floats2half2_rn(acc[nt][0] + bx, acc[nt][1] + by);
        __half2 p1 = __floats2half2_rn(acc[nt][2] + bx, acc[nt][3] + by);
        *(uint32_t*)(smem + OFF_XL + ((size_t)R0 * XS + col) * 2) = *(uint32_t*)&p0;
        *(uint32_t*)(smem + OFF_XL + ((size_t)R1 * XS + col) * 2) = *(uint32_t*)&p1;
    }
    __syncthreads();

    // ---- combine from smem V -> g_Whb (bf16) ----
    const int n0 = base + R0, n1 = base + R1;
    __nv_bfloat16* op0 = g_Whb + ((size_t)e * NN + n0) * DD;
    __nv_bfloat16* op1 = g_Whb + ((size_t)e * NN + n1) * DD;
#pragma unroll
    for (int nt = 0; nt < 8; nt++) {
        int col = nh * 64 + nt * 8 + 2 * c;            // global out col
        int h2 = col >> 5;
        int d  = col & 31;
        float o00 = 0.f, o01 = 0.f, o10 = 0.f, o11 = 0.f;
#pragma unroll
        for (int g2 = 0; g2 < 4; g2++) {
            float a0 = sScf[R0 * 16 + h2 * 4 + g2];
            float a1 = sScf[R1 * 16 + h2 * 4 + g2];
            float2 v0 = __half22float2(*(const __half2*)(smem + OFF_XL + ((size_t)R0 * XS + g2 * 32 + d) * 2));
            float2 v1 = __half22float2(*(const __half2*)(smem + OFF_XL + ((size_t)R1 * XS + g2 * 32 + d) * 2));
            o00 += a0 * v0.x; o01 += a0 * v0.y;
            o10 += a1 * v1.x; o11 += a1 * v1.y;
        }
        if (n0 < NN) {
            __nv_bfloat162 pk = __floats2bfloat162_rn(o00, o01);
            *(uint32_t*)(op0 + col) = *(uint32_t*)&pk;
        }
        if (n1 < NN) {
            __nv_bfloat162 pk = __floats2bfloat162_rn(o10, o11);
            *(uint32_t*)(op1 + col) = *(uint32_t*)&pk;
        }
    }
}

// ================= CSR build =================
__global__ void cnt_zero_kernel() {
    int i = blockIdx.x * 1024 + threadIdx.x;
    if (i < NET * NN) g_cnt[i] = 0;
}
__global__ void cnt_kernel(const int* __restrict__ dst) {
    int e = blockIdx.y;
    int i = blockIdx.x * blockDim.x + threadIdx.x;
    if (i < EE) atomicAdd(&g_cnt[e * NN + dst[(size_t)e * EE + i]], 1);
}
__global__ void scan_a_kernel() {
    __shared__ int wsum[32];
    int t = threadIdx.x, lane = t & 31, wid = t >> 5;
    int gid = blockIdx.x * 1024 + t;
    int v = (gid < NET * NN) ? g_cnt[gid] : 0;
    int x = v;
#pragma unroll
    for (int o = 1; o < 32; o <<= 1) { int y = __shfl_up_sync(0xffffffffu, x, o); if (lane >= o) x += y; }
    if (lane == 31) wsum[wid] = x;
    __syncthreads();
    if (wid == 0) {
        int s = wsum[lane];
#pragma unroll
        for (int o = 1; o < 32; o <<= 1) { int y = __shfl_up_sync(0xffffffffu, s, o); if (lane >= o) s += y; }
        wsum[lane] = s;
    }
    __syncthreads();
    int pfx = wid ? wsum[wid - 1] : 0;
    if (gid < NET * NN) g_off[gid] = pfx + x - v;
    if (t == 1023) g_bsum[blockIdx.x] = pfx + x;
}
__global__ void scan_b_kernel() {
    __shared__ int wsum[8];
    int t = threadIdx.x, lane = t & 31, wid = t >> 5;
    int v = (t < 196) ? g_bsum[t] : 0;
    int x = v;
#pragma unroll
    for (int o = 1; o < 32; o <<= 1) { int y = __shfl_up_sync(0xffffffffu, x, o); if (lane >= o) x += y; }
    if (lane == 31) wsum[wid] = x;
    __syncthreads();
    if (t == 0) {
        int run = 0;
#pragma unroll
        for (int i = 0; i < 8; i++) { int tmp = wsum[i]; wsum[i] = run; run += tmp; }
    }
    __syncthreads();
    if (t < 196) g_bsum[t] = wsum[wid] + x - v;
}
__global__ void scan_c_kernel() {
    int gid = blockIdx.x * 1024 + threadIdx.x;
    if (gid < NET * NN) {
        int o = g_off[gid] + g_bsum[gid >> 10];
        g_off[gid] = o;
        g_cur[gid] = o;
    }
    if (gid == 0) g_off[NET * NN] = NET * EE;
}
__global__ void fill_kernel(const int* __restrict__ src, const int* __restrict__ dst) {
    int e = blockIdx.y;
    int i = blockIdx.x * blockDim.x + threadIdx.x;
    if (i < EE) {
        int d = dst[(size_t)e * EE + i];
        int pos = atomicAdd(&g_cur[e * NN + d], 1);
        g_sorted[pos] = src[(size_t)e * EE + i];
    }
}

// ================= fused gather (bf16) + mean + residual + LayerNorm =================
__global__ void gather_ln_kernel(const float* __restrict__ feat,
                                 const float* __restrict__ ln_g, const float* __restrict__ ln_b,
                                 float* __restrict__ out) {
    int w    = (blockIdx.x * blockDim.x + threadIdx.x) >> 5;
    int lane = threadIdx.x & 31;
    if (w >= NN) return;
    float a0 = 0.f, a1 = 0.f, a2 = 0.f, a3 = 0.f;
#pragma unroll
    for (int e = 0; e < NET; e++) {
        int beg = g_off[e * NN + w], end = g_off[e * NN + w + 1];
        const __nv_bfloat16* WhE = g_Whb + (size_t)e * NN * DD + lane * 4;
        float t0 = 0.f, t1 = 0.f, t2 = 0.f, t3 = 0.f;
        int i = beg;
        for (; i + 2 <= end; i += 2) {
            int s0 = __ldg(&g_sorted[i]), s1 = __ldg(&g_sorted[i + 1]);
            uint2 u0 = *(const uint2*)(WhE + (size_t)s0 * DD);
            uint2 u1 = *(const uint2*)(WhE + (size_t)s1 * DD);
            float2 p0 = __bfloat1622float2(*(__nv_bfloat162*)&u0.x);
            float2 p1 = __bfloat1622float2(*(__nv_bfloat162*)&u0.y);
            float2 q0 = __bfloat1622float2(*(__nv_bfloat162*)&u1.x);
            float2 q1 = __bfloat1622float2(*(__nv_bfloat162*)&u1.y);
            t0 += p0.x + q0.x; t1 += p0.y + q0.y;
            t2 += p1.x + q1.x; t3 += p1.y + q1.y;
        }
        if (i < end) {
            int s0 = __ldg(&g_sorted[i]);
            uint2 u0 = *(const uint2*)(WhE + (size_t)s0 * DD);
            float2 p0 = __bfloat1622float2(*(__nv_bfloat162*)&u0.x);
            float2 p1 = __bfloat1622float2(*(__nv_bfloat162*)&u0.y);
            t0 += p0.x; t1 += p0.y; t2 += p1.x; t3 += p1.y;
        }
        float inv = 1.f / fmaxf((float)(end - beg), 1.f);
        a0 += t0 * inv; a1 += t1 * inv; a2 += t2 * inv; a3 += t3 * inv;
    }
    float4 f = ((const float4*)(feat + (size_t)w * DD))[lane];
    float4 h = make_float4(a0 + f.x, a1 + f.y, a2 + f.z, a3 + f.w);

    float s = h.x + h.y + h.z + h.w;
#pragma unroll
    for (int o = 16; o; o >>= 1) s += __shfl_xor_sync(0xffffffffu, s, o);
    float mu = s * (1.0f / 128.0f);

    float dx = h.x - mu, dy = h.y - mu, dz = h.z - mu, dw = h.w - mu;
    float q = dx * dx + dy * dy + dz * dz + dw * dw;
#pragma unroll
    for (int o = 16; o; o >>= 1) q += __shfl_xor_sync(0xffffffffu, q, o);
    float inv = rsqrtf(q * (1.0f / 128.0f) + LN_EPS);

    float4 gg = ((const float4*)ln_g)[lane];
    float4 bb = ((const float4*)ln_b)[lane];
    float4 o4 = make_float4(dx * inv * gg.x + bb.x, dy * inv * gg.y + bb.y,
                            dz * inv * gg.z + bb.z, dw * inv * gg.w + bb.w);
    ((float4*)out)[(size_t)w * 32 + lane] = o4;
}

extern "C" void kernel_launch(void* const* d_in, const int* in_sizes, int n_in,
                              void* d_out, int out_size) {
    const float* feat = (const float*)d_in[0];
    const int*   src  = (const int*)d_in[1];
    const int*   dst  = (const int*)d_in[2];
    const float* Wt   = (const float*)d_in[3];
    const float* bt   = (const float*)d_in[4];
    const float* Kw   = (const float*)d_in[5];
    const float* Kb   = (const float*)d_in[6];
    const float* Qw   = (const float*)d_in[7];
    const float* Qb   = (const float*)d_in[8];
    const float* Vw   = (const float*)d_in[9];
    const float* Vb   = (const float*)d_in[10];
    const float* ln_g = (const float*)d_in[11];
    const float* ln_b = (const float*)d_in[12];
    float* out = (float*)d_out;

    cudaFuncSetAttribute(transform_kernel, cudaFuncAttributeMaxDynamicSharedMemorySize, SMEM_BYTES);

    wsplit_kernel<<<dim3(256, NET), 256>>>(Wt, Kw, Qw, Vw);
    cnt_zero_kernel<<<196, 1024>>>();
    cnt_kernel<<<dim3(EE / 256, NET), 256>>>(dst);
    scan_a_kernel<<<196, 1024>>>();
    scan_b_kernel<<<1, 256>>>();
    scan_c_kernel<<<196, 1024>>>();
    fill_kernel<<<dim3(EE / 256, NET), 256>>>(src, dst);

    transform_kernel<<<dim3((NN + TM - 1) / TM, NET), 256, SMEM_BYTES>>>(
        feat, bt, Kb, Qb, Vb);

    gather_ln_kernel<<<(NN * 32 + 255) / 256, 256>>>(feat, ln_g, ln_b, out);
}

// round 10
// speedup vs baseline: 1.0078x; 1.0078x over previous
#include <cuda_runtime.h>
#include <cuda_bf16.h>
#include <cuda_fp16.h>
#include <cstdint>

#define NN   100000
#define DD   128
#define EE   800000
#define NET  2
#define TM   128
#define LN_EPS 1e-5f

#define XS 136          // fp16 row stride (272B -> conflict-free ldmatrix)
#define LODELTA 34816   // XH -> XL plane delta (128*136*2)

// ---- smem byte offsets (transform) ----
#define OFF_XH 0
#define OFF_XL 34816        // feat lo (preserved whole kernel)
#define OFF_K  69632        // fp16 K stage
#define OFF_W0 104448
#define OFF_W1 139264
#define OFF_SC 174080       // 128*16 fp32 = 8KB
#define OFF_BI 182272       // 384 fp32
#define SMEM_BYTES 183808

// ---- scratch (device globals) ----
__device__ __nv_bfloat16 g_Whb[(size_t)NET * NN * DD];   // bf16 messages
__device__ __half g_Wc[NET * 3 * DD * DD];               // composite fp16 weights [e][K,Q,V][128][128]
__device__ float g_bias[NET * 3 * DD];                   // composite biases
__device__ int g_cnt[NET * NN];
__device__ int g_off[NET * NN + 1];
__device__ int g_cur[NET * NN];
__device__ int g_bsum[256];
__device__ int g_sorted[NET * EE];

// ---- warp MMA primitives ----
__device__ __forceinline__ void ldmat4(uint32_t* r, uint32_t addr) {
    asm volatile("ldmatrix.sync.aligned.m8n8.x4.shared.b16 {%0,%1,%2,%3}, [%4];"
        : "=r"(r[0]), "=r"(r[1]), "=r"(r[2]), "=r"(r[3]) : "r"(addr));
}
__device__ __forceinline__ void ldmat4t(uint32_t* r, uint32_t addr) {
    asm volatile("ldmatrix.sync.aligned.m8n8.x4.trans.shared.b16 {%0,%1,%2,%3}, [%4];"
        : "=r"(r[0]), "=r"(r[1]), "=r"(r[2]), "=r"(r[3]) : "r"(addr));
}
__device__ __forceinline__ void mma16816(float* c, const uint32_t* a, const uint32_t* b) {
    asm volatile("mma.sync.aligned.m16n8k16.row.col.f32.f16.f16.f32 "
        "{%0,%1,%2,%3}, {%4,%5,%6,%7}, {%8,%9}, {%0,%1,%2,%3};"
        : "+f"(c[0]), "+f"(c[1]), "+f"(c[2]), "+f"(c[3])
        : "r"(a[0]), "r"(a[1]), "r"(a[2]), "r"(a[3]), "r"(b[0]), "r"(b[1]));
}
#define CP_COMMIT() asm volatile("cp.async.commit_group;" ::: "memory")
#define CP_WAIT(n)  asm volatile("cp.async.wait_group %0;" :: "n"(n) : "memory")

__device__ __forceinline__ void split2h(float a, float b, uint32_t& hi, uint32_t& lo) {
    __half ha = __float2half_rn(a), hb = __float2half_rn(b);
    __half la = __float2half_rn(a - __half2float(ha));
    __half lb = __float2half_rn(b - __half2float(hb));
    __half2 h; h.x = ha; h.y = hb;
    __half2 l; l.x = la; l.y = lb;
    hi = *(uint32_t*)&h; lo = *(uint32_t*)&l;
}

// cp.async one 32KB fp16 weight matrix into XS-strided smem
__device__ __forceinline__ void cpw(uint32_t sb, int offW, const __half* __restrict__ gsrc, int t) {
#pragma unroll
    for (int i = 0; i < 8; i++) {
        int u = i * 256 + t;
        int k = u >> 4, n16 = u & 15;
        uint32_t dh = sb + offW + k * (XS * 2) + n16 * 16;
        const char* gh = (const char*)gsrc + k * 256 + n16 * 16;
        asm volatile("cp.async.cg.shared.global [%0], [%1], 16;" :: "r"(dh), "l"(gh));
    }
}

// fp16 GEMM, warp tile M16 x N128: ALO -> (Xh + Xl)*Wh ; else Xh*Wh
template<bool ALO>
__device__ __forceinline__ void wgemm(char* smem, float acc[16][4], int offW, int w, int lane) {
    const int r = lane & 7, sel = lane >> 3;
    const int rowoff = (sel & 1) ? 8 : 0;
    const int coloff = (sel & 2) ? 8 : 0;
    const uint32_t sb = (uint32_t)__cvta_generic_to_shared(smem);
    const int arow = 16 * w + r + rowoff;
    const uint32_t axh = sb + OFF_XH + (uint32_t)(arow * XS + coloff) * 2;
#pragma unroll
    for (int kk = 0; kk < 8; kk++) {
        uint32_t Ah[4], Al[4];
        ldmat4(Ah, axh + kk * 32);
        if (ALO) ldmat4(Al, axh + LODELTA + kk * 32);
        const int brow = kk * 16 + r + rowoff;
        const uint32_t bh = sb + offW + (uint32_t)(brow * XS + coloff) * 2;
#pragma unroll
        for (int nt16 = 0; nt16 < 8; nt16++) {
            uint32_t Bh[4];
            ldmat4t(Bh, bh + nt16 * 32);
            mma16816(acc[2 * nt16],     Ah, Bh);
            mma16816(acc[2 * nt16 + 1], Ah, Bh + 2);
            if (ALO) {
                mma16816(acc[2 * nt16],     Al, Bh);
                mma16816(acc[2 * nt16 + 1], Al, Bh + 2);
            }
        }
    }
}

__device__ __forceinline__ void zacc(float acc[16][4]) {
#pragma unroll
    for (int i = 0; i < 16; i++) { acc[i][0] = acc[i][1] = acc[i][2] = acc[i][3] = 0.f; }
}

// ---- composite weight prep: Wc[mat] = Wt @ {Kw,Qw,Vw} (fp32 -> fp16) ----
// grid (12, NET): blockIdx.x = mat*4 + col quarter; 256 thr; smem 80KB
__global__ void __launch_bounds__(256) wprep_kernel(
    const float* __restrict__ Wt, const float* __restrict__ Kw,
    const float* __restrict__ Qw, const float* __restrict__ Vw)
{
    int q = blockIdx.x & 3, mat = blockIdx.x >> 2;
    int e = blockIdx.y;
    const float* srcs[3] = {Kw, Qw, Vw};
    const float* A = Wt + (size_t)e * 16384;          // [k][j]
    const float* B = srcs[mat] + (size_t)e * 16384;   // [j][n]
    extern __shared__ float s[];
    float* sA = s;            // 128x128
    float* sB = s + 16384;    // 128x32 (cols q*32..q*32+31)
    int t = threadIdx.x;
    for (int i = t; i < 4096; i += 256) ((float4*)sA)[i] = ((const float4*)A)[i];
    for (int i = t; i < 1024; i += 256) {
        int j = i >> 3, cc = (i & 7) * 4;
        *(float4*)(sB + j * 32 + cc) = *(const float4*)(B + (size_t)j * 128 + q * 32 + cc);
    }
    __syncthreads();
    int r0 = (t >> 2) * 2, c0 = (t & 3) * 8;          // 2 rows x 8 cols
    float acc0[8] = {0,0,0,0,0,0,0,0}, acc1[8] = {0,0,0,0,0,0,0,0};
    for (int j = 0; j < 128; j++) {
        float a0 = sA[r0 * 128 + j], a1 = sA[(r0 + 1) * 128 + j];
        float4 b0 = *(float4*)(sB + j * 32 + c0);
        float4 b1 = *(float4*)(sB + j * 32 + c0 + 4);
        acc0[0] += a0 * b0.x; acc0[1] += a0 * b0.y; acc0[2] += a0 * b0.z; acc0[3] += a0 * b0.w;
        acc0[4] += a0 * b1.x; acc0[5] += a0 * b1.y; acc0[6] += a0 * b1.z; acc0[7] += a0 * b1.w;
        acc1[0] += a1 * b0.x; acc1[1] += a1 * b0.y; acc1[2] += a1 * b0.z; acc1[3] += a1 * b0.w;
        acc1[4] += a1 * b1.x; acc1[5] += a1 * b1.y; acc1[6] += a1 * b1.z; acc1[7] += a1 * b1.w;
    }
    __half* C = g_Wc + (size_t)(e * 3 + mat) * 16384;
#pragma unroll
    for (int cc = 0; cc < 8; cc += 2) {
        __half2 p0 = __floats2half2_rn(acc0[cc], acc0[cc + 1]);
        __half2 p1 = __floats2half2_rn(acc1[cc], acc1[cc + 1]);
        *(uint32_t*)(C + (size_t)r0 * 128 + q * 32 + c0 + cc) = *(uint32_t*)&p0;
        *(uint32_t*)(C + (size_t)(r0 + 1) * 128 + q * 32 + c0 + cc) = *(uint32_t*)&p1;
    }
}

// ---- composite biases: b[mat] = bt @ {Kw,Qw,Vw} + {Kb,Qb,Vb} ----
__global__ void bprep_kernel(const float* __restrict__ bt,
                             const float* __restrict__ Kw, const float* __restrict__ Kb,
                             const float* __restrict__ Qw, const float* __restrict__ Qb,
                             const float* __restrict__ Vw, const float* __restrict__ Vb)
{
    int mat = blockIdx.x % 3, e = blockIdx.x / 3;
    const float* srcs[3] = {Kw, Qw, Vw};
    const float* bsrc[3] = {Kb, Qb, Vb};
    int n = threadIdx.x;
    const float* B = srcs[mat] + (size_t)e * 16384;
    float s = bsrc[mat][e * 128 + n];
    for (int j = 0; j < 128; j++) s += bt[e * 128 + j] * B[(size_t)j * 128 + n];
    g_bias[(e * 3 + mat) * 128 + n] = s;
}

// ================= fused transform: 3 independent GEMMs from feat =================
__global__ void __launch_bounds__(256, 1) transform_kernel(const float* __restrict__ feat)
{
    extern __shared__ char smem[];
    const uint32_t sb = (uint32_t)__cvta_generic_to_shared(smem);
    const int e    = blockIdx.y;
    const int base = blockIdx.x * TM;
    const int t    = threadIdx.x;
    const int w = t >> 5, lane = t & 31;
    const int g = lane >> 2, c = lane & 3;
    const int R0 = 16 * w + g, R1 = R0 + 8;
    float* sScf = (float*)(smem + OFF_SC);
    float* sBI  = (float*)(smem + OFF_BI);
    const __half* Wb = g_Wc + (size_t)e * 3 * 16384;

    cpw(sb, OFF_W0, Wb,         t); CP_COMMIT();   // WcK
    cpw(sb, OFF_W1, Wb + 16384, t); CP_COMMIT();   // WcQ

    if (t < 128) {
        sBI[t]       = g_bias[(e * 3 + 0) * 128 + t];
        sBI[128 + t] = g_bias[(e * 3 + 1) * 128 + t];
        sBI[256 + t] = g_bias[(e * 3 + 2) * 128 + t];
    }

    // feat -> X (fp16 hi/lo), overlapped with weight cp.async
#pragma unroll
    for (int i = 0; i < 16; i++) {
        int u = i * 256 + t;
        int m = u >> 5, k = (u & 31) * 4;
        int node = base + m;
        float4 v = make_float4(0.f, 0.f, 0.f, 0.f);
        if (node < NN) v = *(const float4*)(feat + (size_t)node * DD + k);
        uint32_t h0, l0, h1, l1;
        split2h(v.x, v.y, h0, l0);
        split2h(v.z, v.w, h1, l1);
        *(uint2*)(smem + OFF_XH + ((size_t)m * XS + k) * 2) = make_uint2(h0, h1);
        *(uint2*)(smem + OFF_XL + ((size_t)m * XS + k) * 2) = make_uint2(l0, l1);
    }
    CP_WAIT(1);                                    // WcK ready
    __syncthreads();

    float acc[16][4];

    // ---- GEMM K (hi-only): K = feat @ WcK ----
    zacc(acc);
    wgemm<false>(smem, acc, OFF_W0, w, lane);
    __syncthreads();                               // W0 reads done

    // stage K (+bK) -> OFF_K fp16; start WcV -> W0
#pragma unroll
    for (int nt = 0; nt < 16; nt++) {
        int col = nt * 8 + 2 * c;
        float bx = sBI[col], by = sBI[col + 1];
        __half2 p0 = __floats2half2_rn(acc[nt][0] + bx, acc[nt][1] + by);
        __half2 p1 = __floats2half2_rn(acc[nt][2] + bx, acc[nt][3] + by);
        *(uint32_t*)(smem + OFF_K + ((size_t)R0 * XS + col) * 2) = *(uint32_t*)&p0;
        *(uint32_t*)(smem + OFF_K + ((size_t)R1 * XS + col) * 2) = *(uint32_t*)&p1;
    }
    cpw(sb, OFF_W0, Wb + 2 * 16384, t); CP_COMMIT();   // WcV
    CP_WAIT(1);                                        // WcQ ready
    __syncthreads();

    // ---- GEMM Q (hi-only): Q = feat @ WcQ ----
    zacc(acc);
    wgemm<false>(smem, acc, OFF_W1, w, lane);
#pragma unroll
    for (int nt = 0; nt < 16; nt++) {
        int col = nt * 8 + 2 * c;
        float bx = sBI[128 + col], by = sBI[128 + col + 1];
        acc[nt][0] += bx; acc[nt][1] += by;
        acc[nt][2] += bx; acc[nt][3] += by;
    }

    // ---- scores (K from fp16 OFF_K) ----
    const float scale = 0.17677669529663687f;
#pragma unroll
    for (int gp = 0; gp < 4; gp++) {
        float2 kv0[4], kv1[4];
#pragma unroll
        for (int j = 0; j < 4; j++) {
            __half2 k0 = *(const __half2*)(smem + OFF_K + ((size_t)R0 * XS + gp * 32 + j * 8 + 2 * c) * 2);
            __half2 k1 = *(const __half2*)(smem + OFF_K + ((size_t)R1 * XS + gp * 32 + j * 8 + 2 * c) * 2);
            kv0[j] = __half22float2(k0);
            kv1[j] = __half22float2(k1);
        }
#pragma unroll
        for (int h = 0; h < 4; h++) {
            float p0 = 0.f, p1 = 0.f;
#pragma unroll
            for (int j = 0; j < 4; j++) {
                p0 += acc[4 * h + j][0] * kv0[j].x + acc[4 * h + j][1] * kv0[j].y;
                p1 += acc[4 * h + j][2] * kv1[j].x + acc[4 * h + j][3] * kv1[j].y;
            }
            p0 += __shfl_xor_sync(0xffffffffu, p0, 1);
            p0 += __shfl_xor_sync(0xffffffffu, p0, 2);
            p1 += __shfl_xor_sync(0xffffffffu, p1, 1);
            p1 += __shfl_xor_sync(0xffffffffu, p1, 2);
            if (c == 0) {
                sScf[R0 * 16 + h * 4 + gp] = p0 * scale;
                sScf[R1 * 16 + h * 4 + gp] = p1 * scale;
            }
        }
    }
    __syncthreads();

    // ---- softmax ----
#pragma unroll
    for (int i = 0; i < 2; i++) {
        int p = t * 2 + i;
        int row = p >> 2, h = p & 3;
        float4 s = *(float4*)(sScf + row * 16 + h * 4);
        float m = fmaxf(fmaxf(s.x, s.y), fmaxf(s.z, s.w));
        float e0 = __expf(s.x - m), e1 = __expf(s.y - m), e2 = __expf(s.z - m), e3 = __expf(s.w - m);
        float inv = 1.f / (e0 + e1 + e2 + e3);
        *(float4*)(sScf + row * 16 + h * 4) = make_float4(e0 * inv, e1 * inv, e2 * inv, e3 * inv);
    }
    CP_WAIT(0);                                        // WcV ready
    __syncthreads();

    // ---- GEMM V (2-pass, activation-corrected): V = (Xh+Xl) @ WcV ----
    zacc(acc);
    wgemm<true>(smem, acc, OFF_W0, w, lane);
#pragma unroll
    for (int nt = 0; nt < 16; nt++) {
        int col = nt * 8 + 2 * c;
        float bx = sBI[256 + col], by = sBI[256 + col + 1];
        acc[nt][0] += bx; acc[nt][1] += by;
        acc[nt][2] += bx; acc[nt][3] += by;
    }

    // ---- combine (register-local) -> g_Whb (bf16) ----
    const int n0 = base + R0, n1 = base + R1;
    __nv_bfloat16* op0 = g_Whb + ((size_t)e * NN + n0) * DD;
    __nv_bfloat16* op1 = g_Whb + ((size_t)e * NN + n1) * DD;
#pragma unroll
    for (int h = 0; h < 4; h++) {
        float4 a0 = *(float4*)(sScf + R0 * 16 + 4 * h);
        float4 a1 = *(float4*)(sScf + R1 * 16 + 4 * h);
#pragma unroll
        for (int j3 = 0; j3 < 4; j3++) {
            int col = (h * 4 + j3) * 8 + 2 * c;
            float o00 = a0.x * acc[j3][0]      + a0.y * acc[4 + j3][0]
                      + a0.z * acc[8 + j3][0]  + a0.w * acc[12 + j3][0];
            float o01 = a0.x * acc[j3][1]      + a0.y * acc[4 + j3][1]
                      + a0.z * acc[8 + j3][1]  + a0.w * acc[12 + j3][1];
            float o10 = a1.x * acc[j3][2]      + a1.y * acc[4 + j3][2]
                      + a1.z * acc[8 + j3][2]  + a1.w * acc[12 + j3][2];
            float o11 = a1.x * acc[j3][3]      + a1.y * acc[4 + j3][3]
                      + a1.z * acc[8 + j3][3]  + a1.w * acc[12 + j3][3];
            if (n0 < NN) {
                __nv_bfloat162 pk = __floats2bfloat162_rn(o00, o01);
                *(uint32_t*)(op0 + col) = *(uint32_t*)&pk;
            }
            if (n1 < NN) {
                __nv_bfloat162 pk = __floats2bfloat162_rn(o10, o11);
                *(uint32_t*)(op1 + col) = *(uint32_t*)&pk;
            }
        }
    }
}

// ================= CSR build =================
__global__ void cnt_zero_kernel() {
    int i = blockIdx.x * 1024 + threadIdx.x;
    if (i < NET * NN) g_cnt[i] = 0;
}
__global__ void cnt_kernel(const int* __restrict__ dst) {
    int e = blockIdx.y;
    int i = blockIdx.x * blockDim.x + threadIdx.x;
    if (i < EE) atomicAdd(&g_cnt[e * NN + dst[(size_t)e * EE + i]], 1);
}
__global__ void scan_a_kernel() {
    __shared__ int wsum[32];
    int t = threadIdx.x, lane = t & 31, wid = t >> 5;
    int gid = blockIdx.x * 1024 + t;
    int v = (gid < NET * NN) ? g_cnt[gid] : 0;
    int x = v;
#pragma unroll
    for (int o = 1; o < 32; o <<= 1) { int y = __shfl_up_sync(0xffffffffu, x, o); if (lane >= o) x += y; }
    if (lane == 31) wsum[wid] = x;
    __syncthreads();
    if (wid == 0) {
        int s = wsum[lane];
#pragma unroll
        for (int o = 1; o < 32; o <<= 1) { int y = __shfl_up_sync(0xffffffffu, s, o); if (lane >= o) s += y; }
        wsum[lane] = s;
    }
    __syncthreads();
    int pfx = wid ? wsum[wid - 1] : 0;
    if (gid < NET * NN) g_off[gid] = pfx + x - v;
    if (t == 1023) g_bsum[blockIdx.x] = pfx + x;
}
__global__ void scan_b_kernel() {
    __shared__ int wsum[8];
    int t = threadIdx.x, lane = t & 31, wid = t >> 5;
    int v = (t < 196) ? g_bsum[t] : 0;
    int x = v;
#pragma unroll
    for (int o = 1; o < 32; o <<= 1) { int y = __shfl_up_sync(0xffffffffu, x, o); if (lane >= o) x += y; }
    if (lane == 31) wsum[wid] = x;
    __syncthreads();
    if (t == 0) {
        int run = 0;
#pragma unroll
        for (int i = 0; i < 8; i++) { int tmp = wsum[i]; wsum[i] = run; run += tmp; }
    }
    __syncthreads();
    if (t < 196) g_bsum[t] = wsum[wid] + x - v;
}
__global__ void scan_c_kernel() {
    int gid = blockIdx.x * 1024 + threadIdx.x;
    if (gid < NET * NN) {
        int o = g_off[gid] + g_bsum[gid >> 10];
        g_off[gid] = o;
        g_cur[gid] = o;
    }
    if (gid == 0) g_off[NET * NN] = NET * EE;
}
__global__ void fill_kernel(const int* __restrict__ src, const int* __restrict__ dst) {
    int e = blockIdx.y;
    int i = blockIdx.x * blockDim.x + threadIdx.x;
    if (i < EE) {
        int d = dst[(size_t)e * EE + i];
        int pos = atomicAdd(&g_cur[e * NN + d], 1);
        g_sorted[pos] = src[(size_t)e * EE + i];
    }
}

// ================= fused gather (bf16) + mean + residual + LayerNorm =================
__global__ void gather_ln_kernel(const float* __restrict__ feat,
                                 const float* __restrict__ ln_g, const float* __restrict__ ln_b,
                                 float* __restrict__ out) {
    int w    = (blockIdx.x * blockDim.x + threadIdx.x) >> 5;
    int lane = threadIdx.x & 31;
    if (w >= NN) return;
    float a0 = 0.f, a1 = 0.f, a2 = 0.f, a3 = 0.f;
#pragma unroll
    for (int e = 0; e < NET; e++) {
        int beg = g_off[e * NN + w], end = g_off[e * NN + w + 1];
        const __nv_bfloat16* WhE = g_Whb + (size_t)e * NN * DD + lane * 4;
        float t0 = 0.f, t1 = 0.f, t2 = 0.f, t3 = 0.f;
        int i = beg;
        for (; i + 2 <= end; i += 2) {
            int s0 = __ldg(&g_sorted[i]), s1 = __ldg(&g_sorted[i + 1]);
            uint2 u0 = *(const uint2*)(WhE + (size_t)s0 * DD);
            uint2 u1 = *(const uint2*)(WhE + (size_t)s1 * DD);
            float2 p0 = __bfloat1622float2(*(__nv_bfloat162*)&u0.x);
            float2 p1 = __bfloat1622float2(*(__nv_bfloat162*)&u0.y);
            float2 q0 = __bfloat1622float2(*(__nv_bfloat162*)&u1.x);
            float2 q1 = __bfloat1622float2(*(__nv_bfloat162*)&u1.y);
            t0 += p0.x + q0.x; t1 += p0.y + q0.y;
            t2 += p1.x + q1.x; t3 += p1.y + q1.y;
        }
        if (i < end) {
            int s0 = __ldg(&g_sorted[i]);
            uint2 u0 = *(const uint2*)(WhE + (size_t)s0 * DD);
            float2 p0 = __bfloat1622float2(*(__nv_bfloat162*)&u0.x);
            float2 p1 = __bfloat1622float2(*(__nv_bfloat162*)&u0.y);
            t0 += p0.x; t1 += p0.y; t2 += p1.x; t3 += p1.y;
        }
        float inv = 1.f / fmaxf((float)(end - beg), 1.f);
        a0 += t0 * inv; a1 += t1 * inv; a2 += t2 * inv; a3 += t3 * inv;
    }
    float4 f = ((const float4*)(feat + (size_t)w * DD))[lane];
    float4 h = make_float4(a0 + f.x, a1 + f.y, a2 + f.z, a3 + f.w);

    float s = h.x + h.y + h.z + h.w;
#pragma unroll
    for (int o = 16; o; o >>= 1) s += __shfl_xor_sync(0xffffffffu, s, o);
    float mu = s * (1.0f / 128.0f);

    float dx = h.x - mu, dy = h.y - mu, dz = h.z - mu, dw = h.w - mu;
    float q = dx * dx + dy * dy + dz * dz + dw * dw;
#pragma unroll
    for (int o = 16; o; o >>= 1) q += __shfl_xor_sync(0xffffffffu, q, o);
    float inv = rsqrtf(q * (1.0f / 128.0f) + LN_EPS);

    float4 gg = ((const float4*)ln_g)[lane];
    float4 bb = ((const float4*)ln_b)[lane];
    float4 o4 = make_float4(dx * inv * gg.x + bb.x, dy * inv * gg.y + bb.y,
                            dz * inv * gg.z + bb.z, dw * inv * gg.w + bb.w);
    ((float4*)out)[(size_t)w * 32 + lane] = o4;
}

extern "C" void kernel_launch(void* const* d_in, const int* in_sizes, int n_in,
                              void* d_out, int out_size) {
    const float* feat = (const float*)d_in[0];
    const int*   src  = (const int*)d_in[1];
    const int*   dst  = (const int*)d_in[2];
    const float* Wt   = (const float*)d_in[3];
    const float* bt   = (const float*)d_in[4];
    const float* Kw   = (const float*)d_in[5];
    const float* Kb   = (const float*)d_in[6];
    const float* Qw   = (const float*)d_in[7];
    const float* Qb   = (const float*)d_in[8];
    const float* Vw   = (const float*)d_in[9];
    const float* Vb   = (const float*)d_in[10];
    const float* ln_g = (const float*)d_in[11];
    const float* ln_b = (const float*)d_in[12];
    float* out = (float*)d_out;

    cudaFuncSetAttribute(transform_kernel, cudaFuncAttributeMaxDynamicSharedMemorySize, SMEM_BYTES);
    cudaFuncSetAttribute(wprep_kernel, cudaFuncAttributeMaxDynamicSharedMemorySize, 81920);

    wprep_kernel<<<dim3(12, NET), 256, 81920>>>(Wt, Kw, Qw, Vw);
    bprep_kernel<<<NET * 3, 128>>>(bt, Kw, Kb, Qw, Qb, Vw, Vb);
    cnt_zero_kernel<<<196, 1024>>>();
    cnt_kernel<<<dim3(EE / 256, NET), 256>>>(dst);
    scan_a_kernel<<<196, 1024>>>();
    scan_b_kernel<<<1, 256>>>();
    scan_c_kernel<<<196, 1024>>>();
    fill_kernel<<<dim3(EE / 256, NET), 256>>>(src, dst);

    transform_kernel<<<dim3((NN + TM - 1) / TM, NET), 256, SMEM_BYTES>>>(feat);

    gather_ln_kernel<<<(NN * 32 + 255) / 256, 256>>>(feat, ln_g, ln_b, out);
}

// round 14
// speedup vs baseline: 1.0838x; 1.0754x over previous
#include <cuda_runtime.h>
#include <cuda_bf16.h>
#include <cuda_fp16.h>
#include <cstdint>

#define NN   100000
#define DD   128
#define EE   800000
#define NET  2
#define TM   128
#define LN_EPS 1e-5f

#define XS 136          // fp16 row stride (272B -> conflict-free ldmatrix)
#define LODELTA 34816   // XH -> XL plane delta (128*136*2)

// ---- smem byte offsets (transform) ----
#define OFF_XH 0
#define OFF_XL 34816        // feat lo (preserved whole kernel)
#define OFF_K  69632        // fp16 K stage
#define OFF_W0 104448
#define OFF_W1 139264
#define OFF_SC 174080       // 128*16 fp32 = 8KB
#define OFF_BI 182272       // 384 fp32
#define SMEM_BYTES 183808

// ---- scratch (device globals) ----
__device__ __nv_bfloat16 g_Whb[(size_t)NET * NN * DD];   // bf16 messages
__device__ __half g_Wc[NET * 3 * DD * DD];               // composite fp16 weights
__device__ float g_bias[NET * 3 * DD];                   // composite biases
__device__ int g_cnt[NET * NN];
__device__ int g_off[NET * NN + 1];
__device__ int g_cur[NET * NN];
__device__ int g_bsum[256];
__device__ int g_sorted[NET * EE];

// ---- warp MMA primitives ----
__device__ __forceinline__ void ldmat4(uint32_t* r, uint32_t addr) {
    asm volatile("ldmatrix.sync.aligned.m8n8.x4.shared.b16 {%0,%1,%2,%3}, [%4];"
        : "=r"(r[0]), "=r"(r[1]), "=r"(r[2]), "=r"(r[3]) : "r"(addr));
}
__device__ __forceinline__ void ldmat4t(uint32_t* r, uint32_t addr) {
    asm volatile("ldmatrix.sync.aligned.m8n8.x4.trans.shared.b16 {%0,%1,%2,%3}, [%4];"
        : "=r"(r[0]), "=r"(r[1]), "=r"(r[2]), "=r"(r[3]) : "r"(addr));
}
__device__ __forceinline__ void mma16816(float* c, const uint32_t* a, const uint32_t* b) {
    asm volatile("mma.sync.aligned.m16n8k16.row.col.f32.f16.f16.f32 "
        "{%0,%1,%2,%3}, {%4,%5,%6,%7}, {%8,%9}, {%0,%1,%2,%3};"
        : "+f"(c[0]), "+f"(c[1]), "+f"(c[2]), "+f"(c[3])
        : "r"(a[0]), "r"(a[1]), "r"(a[2]), "r"(a[3]), "r"(b[0]), "r"(b[1]));
}
#define CP_COMMIT() asm volatile("cp.async.commit_group;" ::: "memory")
#define CP_WAIT(n)  asm volatile("cp.async.wait_group %0;" :: "n"(n) : "memory")

__device__ __forceinline__ void split2h(float a, float b, uint32_t& hi, uint32_t& lo) {
    __half ha = __float2half_rn(a), hb = __float2half_rn(b);
    __half la = __float2half_rn(a - __half2float(ha));
    __half lb = __float2half_rn(b - __half2float(hb));
    __half2 h; h.x = ha; h.y = hb;
    __half2 l; l.x = la; l.y = lb;
    hi = *(uint32_t*)&h; lo = *(uint32_t*)&l;
}

__device__ __forceinline__ void cpw(uint32_t sb, int offW, const __half* __restrict__ gsrc, int t) {
#pragma unroll
    for (int i = 0; i < 8; i++) {
        int u = i * 256 + t;
        int k = u >> 4, n16 = u & 15;
        uint32_t dh = sb + offW + k * (XS * 2) + n16 * 16;
        const char* gh = (const char*)gsrc + k * 256 + n16 * 16;
        asm volatile("cp.async.cg.shared.global [%0], [%1], 16;" :: "r"(dh), "l"(gh));
    }
}

template<bool ALO>
__device__ __forceinline__ void wgemm(char* smem, float acc[16][4], int offW, int w, int lane) {
    const int r = lane & 7, sel = lane >> 3;
    const int rowoff = (sel & 1) ? 8 : 0;
    const int coloff = (sel & 2) ? 8 : 0;
    const uint32_t sb = (uint32_t)__cvta_generic_to_shared(smem);
    const int arow = 16 * w + r + rowoff;
    const uint32_t axh = sb + OFF_XH + (uint32_t)(arow * XS + coloff) * 2;
#pragma unroll
    for (int kk = 0; kk < 8; kk++) {
        uint32_t Ah[4], Al[4];
        ldmat4(Ah, axh + kk * 32);
        if (ALO) ldmat4(Al, axh + LODELTA + kk * 32);
        const int brow = kk * 16 + r + rowoff;
        const uint32_t bh = sb + offW + (uint32_t)(brow * XS + coloff) * 2;
#pragma unroll
        for (int nt16 = 0; nt16 < 8; nt16++) {
            uint32_t Bh[4];
            ldmat4t(Bh, bh + nt16 * 32);
            mma16816(acc[2 * nt16],     Ah, Bh);
            mma16816(acc[2 * nt16 + 1], Ah, Bh + 2);
            if (ALO) {
                mma16816(acc[2 * nt16],     Al, Bh);
                mma16816(acc[2 * nt16 + 1], Al, Bh + 2);
            }
        }
    }
}

__device__ __forceinline__ void zacc(float acc[16][4]) {
#pragma unroll
    for (int i = 0; i < 16; i++) { acc[i][0] = acc[i][1] = acc[i][2] = acc[i][3] = 0.f; }
}

// ---- composite weight prep: Wc[mat] = Wt @ {Kw,Qw,Vw} (fp32 -> fp16) ----
__global__ void __launch_bounds__(256) wprep_kernel(
    const float* __restrict__ Wt, const float* __restrict__ Kw,
    const float* __restrict__ Qw, const float* __restrict__ Vw)
{
    int q = blockIdx.x & 3, mat = blockIdx.x >> 2;
    int e = blockIdx.y;
    const float* srcs[3] = {Kw, Qw, Vw};
    const float* A = Wt + (size_t)e * 16384;
    const float* B = srcs[mat] + (size_t)e * 16384;
    extern __shared__ float s[];
    float* sA = s;
    float* sB = s + 16384;
    int t = threadIdx.x;
    for (int i = t; i < 4096; i += 256) ((float4*)sA)[i] = ((const float4*)A)[i];
    for (int i = t; i < 1024; i += 256) {
        int j = i >> 3, cc = (i & 7) * 4;
        *(float4*)(sB + j * 32 + cc) = *(const float4*)(B + (size_t)j * 128 + q * 32 + cc);
    }
    __syncthreads();
    int r0 = (t >> 2) * 2, c0 = (t & 3) * 8;
    float acc0[8] = {0,0,0,0,0,0,0,0}, acc1[8] = {0,0,0,0,0,0,0,0};
    for (int j = 0; j < 128; j++) {
        float a0 = sA[r0 * 128 + j], a1 = sA[(r0 + 1) * 128 + j];
        float4 b0 = *(float4*)(sB + j * 32 + c0);
        float4 b1 = *(float4*)(sB + j * 32 + c0 + 4);
        acc0[0] += a0 * b0.x; acc0[1] += a0 * b0.y; acc0[2] += a0 * b0.z; acc0[3] += a0 * b0.w;
        acc0[4] += a0 * b1.x; acc0[5] += a0 * b1.y; acc0[6] += a0 * b1.z; acc0[7] += a0 * b1.w;
        acc1[0] += a1 * b0.x; acc1[1] += a1 * b0.y; acc1[2] += a1 * b0.z; acc1[3] += a1 * b0.w;
        acc1[4] += a1 * b1.x; acc1[5] += a1 * b1.y; acc1[6] += a1 * b1.z; acc1[7] += a1 * b1.w;
    }
    __half* C = g_Wc + (size_t)(e * 3 + mat) * 16384;
#pragma unroll
    for (int cc = 0; cc < 8; cc += 2) {
        __half2 p0 = __floats2half2_rn(acc0[cc], acc0[cc + 1]);
        __half2 p1 = __floats2half2_rn(acc1[cc], acc1[cc + 1]);
        *(uint32_t*)(C + (size_t)r0 * 128 + q * 32 + c0 + cc) = *(uint32_t*)&p0;
        *(uint32_t*)(C + (size_t)(r0 + 1) * 128 + q * 32 + c0 + cc) = *(uint32_t*)&p1;
    }
}

__global__ void bprep_kernel(const float* __restrict__ bt,
                             const float* __restrict__ Kw, const float* __restrict__ Kb,
                             const float* __restrict__ Qw, const float* __restrict__ Qb,
                             const float* __restrict__ Vw, const float* __restrict__ Vb)
{
    int mat = blockIdx.x % 3, e = blockIdx.x / 3;
    const float* srcs[3] = {Kw, Qw, Vw};
    const float* bsrc[3] = {Kb, Qb, Vb};
    int n = threadIdx.x;
    const float* B = srcs[mat] + (size_t)e * 16384;
    float s = bsrc[mat][e * 128 + n];
    for (int j = 0; j < 128; j++) s += bt[e * 128 + j] * B[(size_t)j * 128 + n];
    g_bias[(e * 3 + mat) * 128 + n] = s;
}

// ================= fused transform: 3 independent GEMMs from feat =================
__global__ void __launch_bounds__(256, 1) transform_kernel(const float* __restrict__ feat)
{
    extern __shared__ char smem[];
    const uint32_t sb = (uint32_t)__cvta_generic_to_shared(smem);
    const int e    = blockIdx.y;
    const int base = blockIdx.x * TM;
    const int t    = threadIdx.x;
    const int w = t >> 5, lane = t & 31;
    const int g = lane >> 2, c = lane & 3;
    const int R0 = 16 * w + g, R1 = R0 + 8;
    float* sScf = (float*)(smem + OFF_SC);
    float* sBI  = (float*)(smem + OFF_BI);
    const __half* Wb = g_Wc + (size_t)e * 3 * 16384;

    cpw(sb, OFF_W0, Wb,         t); CP_COMMIT();   // WcK
    cpw(sb, OFF_W1, Wb + 16384, t); CP_COMMIT();   // WcQ

    if (t < 128) {
        sBI[t]       = g_bias[(e * 3 + 0) * 128 + t];
        sBI[128 + t] = g_bias[(e * 3 + 1) * 128 + t];
        sBI[256 + t] = g_bias[(e * 3 + 2) * 128 + t];
    }

#pragma unroll
    for (int i = 0; i < 16; i++) {
        int u = i * 256 + t;
        int m = u >> 5, k = (u & 31) * 4;
        int node = base + m;
        float4 v = make_float4(0.f, 0.f, 0.f, 0.f);
        if (node < NN) v = *(const float4*)(feat + (size_t)node * DD + k);
        uint32_t h0, l0, h1, l1;
        split2h(v.x, v.y, h0, l0);
        split2h(v.z, v.w, h1, l1);
        *(uint2*)(smem + OFF_XH + ((size_t)m * XS + k) * 2) = make_uint2(h0, h1);
        *(uint2*)(smem + OFF_XL + ((size_t)m * XS + k) * 2) = make_uint2(l0, l1);
    }
    CP_WAIT(1);
    __syncthreads();

    float acc[16][4];

    // ---- GEMM K (hi-only) ----
    zacc(acc);
    wgemm<false>(smem, acc, OFF_W0, w, lane);
    __syncthreads();

#pragma unroll
    for (int nt = 0; nt < 16; nt++) {
        int col = nt * 8 + 2 * c;
        float bx = sBI[col], by = sBI[col + 1];
        __half2 p0 = __floats2half2_rn(acc[nt][0] + bx, acc[nt][1] + by);
        __half2 p1 = __floats2half2_rn(acc[nt][2] + bx, acc[nt][3] + by);
        *(uint32_t*)(smem + OFF_K + ((size_t)R0 * XS + col) * 2) = *(uint32_t*)&p0;
        *(uint32_t*)(smem + OFF_K + ((size_t)R1 * XS + col) * 2) = *(uint32_t*)&p1;
    }
    cpw(sb, OFF_W0, Wb + 2 * 16384, t); CP_COMMIT();   // WcV
    CP_WAIT(1);
    __syncthreads();

    // ---- GEMM Q (hi-only) ----
    zacc(acc);
    wgemm<false>(smem, acc, OFF_W1, w, lane);
#pragma unroll
    for (int nt = 0; nt < 16; nt++) {
        int col = nt * 8 + 2 * c;
        float bx = sBI[128 + col], by = sBI[128 + col + 1];
        acc[nt][0] += bx; acc[nt][1] += by;
        acc[nt][2] += bx; acc[nt][3] += by;
    }

    // ---- scores ----
    const float scale = 0.17677669529663687f;
#pragma unroll
    for (int gp = 0; gp < 4; gp++) {
        float2 kv0[4], kv1[4];
#pragma unroll
        for (int j = 0; j < 4; j++) {
            __half2 k0 = *(const __half2*)(smem + OFF_K + ((size_t)R0 * XS + gp * 32 + j * 8 + 2 * c) * 2);
            __half2 k1 = *(const __half2*)(smem + OFF_K + ((size_t)R1 * XS + gp * 32 + j * 8 + 2 * c) * 2);
            kv0[j] = __half22float2(k0);
            kv1[j] = __half22float2(k1);
        }
#pragma unroll
        for (int h = 0; h < 4; h++) {
            float p0 = 0.f, p1 = 0.f;
#pragma unroll
            for (int j = 0; j < 4; j++) {
                p0 += acc[4 * h + j][0] * kv0[j].x + acc[4 * h + j][1] * kv0[j].y;
                p1 += acc[4 * h + j][2] * kv1[j].x + acc[4 * h + j][3] * kv1[j].y;
            }
            p0 += __shfl_xor_sync(0xffffffffu, p0, 1);
            p0 += __shfl_xor_sync(0xffffffffu, p0, 2);
            p1 += __shfl_xor_sync(0xffffffffu, p1, 1);
            p1 += __shfl_xor_sync(0xffffffffu, p1, 2);
            if (c == 0) {
                sScf[R0 * 16 + h * 4 + gp] = p0 * scale;
                sScf[R1 * 16 + h * 4 + gp] = p1 * scale;
            }
        }
    }
    __syncthreads();

    // ---- softmax ----
#pragma unroll
    for (int i = 0; i < 2; i++) {
        int p = t * 2 + i;
        int row = p >> 2, h = p & 3;
        float4 s = *(float4*)(sScf + row * 16 + h * 4);
        float m = fmaxf(fmaxf(s.x, s.y), fmaxf(s.z, s.w));
        float e0 = __expf(s.x - m), e1 = __expf(s.y - m), e2 = __expf(s.z - m), e3 = __expf(s.w - m);
        float inv = 1.f / (e0 + e1 + e2 + e3);
        *(float4*)(sScf + row * 16 + h * 4) = make_float4(e0 * inv, e1 * inv, e2 * inv, e3 * inv);
    }
    CP_WAIT(0);
    __syncthreads();

    // ---- GEMM V (2-pass, activation-corrected) ----
    zacc(acc);
    wgemm<true>(smem, acc, OFF_W0, w, lane);
#pragma unroll
    for (int nt = 0; nt < 16; nt++) {
        int col = nt * 8 + 2 * c;
        float bx = sBI[256 + col], by = sBI[256 + col + 1];
        acc[nt][0] += bx; acc[nt][1] += by;
        acc[nt][2] += bx; acc[nt][3] += by;
    }

    // ---- combine -> g_Whb (bf16) ----
    const int n0 = base + R0, n1 = base + R1;
    __nv_bfloat16* op0 = g_Whb + ((size_t)e * NN + n0) * DD;
    __nv_bfloat16* op1 = g_Whb + ((size_t)e * NN + n1) * DD;
#pragma unroll
    for (int h = 0; h < 4; h++) {
        float4 a0 = *(float4*)(sScf + R0 * 16 + 4 * h);
        float4 a1 = *(float4*)(sScf + R1 * 16 + 4 * h);
#pragma unroll
        for (int j3 = 0; j3 < 4; j3++) {
            int col = (h * 4 + j3) * 8 + 2 * c;
            float o00 = a0.x * acc[j3][0]      + a0.y * acc[4 + j3][0]
                      + a0.z * acc[8 + j3][0]  + a0.w * acc[12 + j3][0];
            float o01 = a0.x * acc[j3][1]      + a0.y * acc[4 + j3][1]
                      + a0.z * acc[8 + j3][1]  + a0.w * acc[12 + j3][1];
            float o10 = a1.x * acc[j3][2]      + a1.y * acc[4 + j3][2]
                      + a1.z * acc[8 + j3][2]  + a1.w * acc[12 + j3][2];
            float o11 = a1.x * acc[j3][3]      + a1.y * acc[4 + j3][3]
                      + a1.z * acc[8 + j3][3]  + a1.w * acc[12 + j3][3];
            if (n0 < NN) {
                __nv_bfloat162 pk = __floats2bfloat162_rn(o00, o01);
                *(uint32_t*)(op0 + col) = *(uint32_t*)&pk;
            }
            if (n1 < NN) {
                __nv_bfloat162 pk = __floats2bfloat162_rn(o10, o11);
                *(uint32_t*)(op1 + col) = *(uint32_t*)&pk;
            }
        }
    }
}

// ================= CSR build =================
__global__ void cnt_zero_kernel() {
    int i = blockIdx.x * 1024 + threadIdx.x;
    if (i < NET * NN) g_cnt[i] = 0;
}
__global__ void cnt_kernel(const int* __restrict__ dst) {
    int e = blockIdx.y;
    int i = blockIdx.x * blockDim.x + threadIdx.x;
    if (i < EE) atomicAdd(&g_cnt[e * NN + dst[(size_t)e * EE + i]], 1);
}
__global__ void scan_a_kernel() {
    __shared__ int wsum[32];
    int t = threadIdx.x, lane = t & 31, wid = t >> 5;
    int gid = blockIdx.x * 1024 + t;
    int v = (gid < NET * NN) ? g_cnt[gid] : 0;
    int x = v;
#pragma unroll
    for (int o = 1; o < 32; o <<= 1) { int y = __shfl_up_sync(0xffffffffu, x, o); if (lane >= o) x += y; }
    if (lane == 31) wsum[wid] = x;
    __syncthreads();
    if (wid == 0) {
        int s = wsum[lane];
#pragma unroll
        for (int o = 1; o < 32; o <<= 1) { int y = __shfl_up_sync(0xffffffffu, s, o); if (lane >= o) s += y; }
        wsum[lane] = s;
    }
    __syncthreads();
    int pfx = wid ? wsum[wid - 1] : 0;
    if (gid < NET * NN) g_off[gid] = pfx + x - v;
    if (t == 1023) g_bsum[blockIdx.x] = pfx + x;
}
__global__ void scan_b_kernel() {
    __shared__ int wsum[8];
    int t = threadIdx.x, lane = t & 31, wid = t >> 5;
    int v = (t < 196) ? g_bsum[t] : 0;
    int x = v;
#pragma unroll
    for (int o = 1; o < 32; o <<= 1) { int y = __shfl_up_sync(0xffffffffu, x, o); if (lane >= o) x += y; }
    if (lane == 31) wsum[wid] = x;
    __syncthreads();
    if (t == 0) {
        int run = 0;
#pragma unroll
        for (int i = 0; i < 8; i++) { int tmp = wsum[i]; wsum[i] = run; run += tmp; }
    }
    __syncthreads();
    if (t < 196) g_bsum[t] = wsum[wid] + x - v;
}
__global__ void scan_c_kernel() {
    int gid = blockIdx.x * 1024 + threadIdx.x;
    if (gid < NET * NN) {
        int o = g_off[gid] + g_bsum[gid >> 10];
        g_off[gid] = o;
        g_cur[gid] = o;
    }
    if (gid == 0) g_off[NET * NN] = NET * EE;
}
__global__ void fill_kernel(const int* __restrict__ src, const int* __restrict__ dst) {
    int e = blockIdx.y;
    int i = blockIdx.x * blockDim.x + threadIdx.x;
    if (i < EE) {
        int d = dst[(size_t)e * EE + i];
        int pos = atomicAdd(&g_cur[e * NN + d], 1);
        g_sorted[pos] = src[(size_t)e * EE + i];
    }
}

// ================= fused gather (bf16, 4-wide MLP) + mean + residual + LayerNorm =================
__global__ void gather_ln_kernel(const float* __restrict__ feat,
                                 const float* __restrict__ ln_g, const float* __restrict__ ln_b,
                                 float* __restrict__ out) {
    int w    = (blockIdx.x * blockDim.x + threadIdx.x) >> 5;
    int lane = threadIdx.x & 31;
    if (w >= NN) return;
    float a0 = 0.f, a1 = 0.f, a2 = 0.f, a3 = 0.f;
#pragma unroll
    for (int e = 0; e < NET; e++) {
        int beg = g_off[e * NN + w], end = g_off[e * NN + w + 1];
        const __nv_bfloat16* WhE = g_Whb + (size_t)e * NN * DD + lane * 4;
        float t0 = 0.f, t1 = 0.f, t2 = 0.f, t3 = 0.f;
        int i = beg;
        for (; i + 4 <= end; i += 4) {
            int s0 = __ldg(&g_sorted[i]),     s1 = __ldg(&g_sorted[i + 1]);
            int s2 = __ldg(&g_sorted[i + 2]), s3 = __ldg(&g_sorted[i + 3]);
            uint2 u0 = *(const uint2*)(WhE + (size_t)s0 * DD);
            uint2 u1 = *(const uint2*)(WhE + (size_t)s1 * DD);
            uint2 u2 = *(const uint2*)(WhE + (size_t)s2 * DD);
            uint2 u3 = *(const uint2*)(WhE + (size_t)s3 * DD);
            float2 p0 = __bfloat1622float2(*(__nv_bfloat162*)&u0.x);
            float2 p1 = __bfloat1622float2(*(__nv_bfloat162*)&u0.y);
            float2 q0 = __bfloat1622float2(*(__nv_bfloat162*)&u1.x);
            float2 q1 = __bfloat1622float2(*(__nv_bfloat162*)&u1.y);
            float2 r0 = __bfloat1622float2(*(__nv_bfloat162*)&u2.x);
            float2 r1 = __bfloat1622float2(*(__nv_bfloat162*)&u2.y);
            float2 v0 = __bfloat1622float2(*(__nv_bfloat162*)&u3.x);
            float2 v1 = __bfloat1622float2(*(__nv_bfloat162*)&u3.y);
            t0 += (p0.x + q0.x) + (r0.x + v0.x);
            t1 += (p0.y + q0.y) + (r0.y + v0.y);
            t2 += (p1.x + q1.x) + (r1.x + v1.x);
            t3 += (p1.y + q1.y) + (r1.y + v1.y);
        }
        for (; i < end; i++) {
            int s0 = __ldg(&g_sorted[i]);
            uint2 u0 = *(const uint2*)(WhE + (size_t)s0 * DD);
            float2 p0 = __bfloat1622float2(*(__nv_bfloat162*)&u0.x);
            float2 p1 = __bfloat1622float2(*(__nv_bfloat162*)&u0.y);
            t0 += p0.x; t1 += p0.y; t2 += p1.x; t3 += p1.y;
        }
        float inv = 1.f / fmaxf((float)(end - beg), 1.f);
        a0 += t0 * inv; a1 += t1 * inv; a2 += t2 * inv; a3 += t3 * inv;
    }
    float4 f = ((const float4*)(feat + (size_t)w * DD))[lane];
    float4 h = make_float4(a0 + f.x, a1 + f.y, a2 + f.z, a3 + f.w);

    float s = h.x + h.y + h.z + h.w;
#pragma unroll
    for (int o = 16; o; o >>= 1) s += __shfl_xor_sync(0xffffffffu, s, o);
    float mu = s * (1.0f / 128.0f);

    float dx = h.x - mu, dy = h.y - mu, dz = h.z - mu, dw = h.w - mu;
    float q = dx * dx + dy * dy + dz * dz + dw * dw;
#pragma unroll
    for (int o = 16; o; o >>= 1) q += __shfl_xor_sync(0xffffffffu, q, o);
    float inv = rsqrtf(q * (1.0f / 128.0f) + LN_EPS);

    float4 gg = ((const float4*)ln_g)[lane];
    float4 bb = ((const float4*)ln_b)[lane];
    float4 o4 = make_float4(dx * inv * gg.x + bb.x, dy * inv * gg.y + bb.y,
                            dz * inv * gg.z + bb.z, dw * inv * gg.w + bb.w);
    ((float4*)out)[(size_t)w * 32 + lane] = o4;
}

extern "C" void kernel_launch(void* const* d_in, const int* in_sizes, int n_in,
                              void* d_out, int out_size) {
    const float* feat = (const float*)d_in[0];
    const int*   src  = (const int*)d_in[1];
    const int*   dst  = (const int*)d_in[2];
    const float* Wt   = (const float*)d_in[3];
    const float* bt   = (const float*)d_in[4];
    const float* Kw   = (const float*)d_in[5];
    const float* Kb   = (const float*)d_in[6];
    const float* Qw   = (const float*)d_in[7];
    const float* Qb   = (const float*)d_in[8];
    const float* Vw   = (const float*)d_in[9];
    const float* Vb   = (const float*)d_in[10];
    const float* ln_g = (const float*)d_in[11];
    const float* ln_b = (const float*)d_in[12];
    float* out = (float*)d_out;

    cudaFuncSetAttribute(transform_kernel, cudaFuncAttributeMaxDynamicSharedMemorySize, SMEM_BYTES);
    cudaFuncSetAttribute(wprep_kernel, cudaFuncAttributeMaxDynamicSharedMemorySize, 81920);

    // Streams/events created ONCE on the first (non-captured correctness) call and
    // reused by the capture call. This keeps the capture call allocation-free, so
    // the post-teardown memory baseline matches (R11 failure: per-call stream pools
    // created DURING capture stayed live after graph destroy). The enqueued kernel
    // DAG is identical on every call — same inputs -> same work -> same output.
    static cudaStream_t sA = nullptr, sB = nullptr;
    static cudaEvent_t evF = nullptr, evA = nullptr, evB = nullptr;
    if (sA == nullptr) {
        cudaStreamCreateWithFlags(&sA, cudaStreamNonBlocking);
        cudaStreamCreateWithFlags(&sB, cudaStreamNonBlocking);
        cudaEventCreateWithFlags(&evF, cudaEventDisableTiming);
        cudaEventCreateWithFlags(&evA, cudaEventDisableTiming);
        cudaEventCreateWithFlags(&evB, cudaEventDisableTiming);
        // Touch both streams once so their device-side pools are materialized
        // now (outside any capture), not lazily during the capture call.
        cnt_zero_kernel<<<1, 32, 0, sA>>>();
        cnt_zero_kernel<<<1, 32, 0, sB>>>();
    }

    cudaEventRecord(evF, 0);
    cudaStreamWaitEvent(sA, evF, 0);
    cudaStreamWaitEvent(sB, evF, 0);

    // Branch A: CSR build (depends only on src/dst)
    cnt_zero_kernel<<<196, 1024, 0, sA>>>();
    cnt_kernel<<<dim3(EE / 256, NET), 256, 0, sA>>>(dst);
    scan_a_kernel<<<196, 1024, 0, sA>>>();
    scan_b_kernel<<<1, 256, 0, sA>>>();
    scan_c_kernel<<<196, 1024, 0, sA>>>();
    fill_kernel<<<dim3(EE / 256, NET), 256, 0, sA>>>(src, dst);
    cudaEventRecord(evA, sA);

    // Branch B: weight prep + transform (depends only on feat/weights)
    wprep_kernel<<<dim3(12, NET), 256, 81920, sB>>>(Wt, Kw, Qw, Vw);
    bprep_kernel<<<NET * 3, 128, 0, sB>>>(bt, Kw, Kb, Qw, Qb, Vw, Vb);
    transform_kernel<<<dim3((NN + TM - 1) / TM, NET), 256, SMEM_BYTES, sB>>>(feat);
    cudaEventRecord(evB, sB);

    // Join, then final gather + LayerNorm on the base stream
    cudaStreamWaitEvent(0, evA, 0);
    cudaStreamWaitEvent(0, evB, 0);
    gather_ln_kernel<<<(NN * 32 + 255) / 256, 256>>>(feat, ln_g, ln_b, out);
}

// round 15
// speedup vs baseline: 1.2994x; 1.1990x over previous
#include <cuda_runtime.h>
#include <cuda_bf16.h>
#include <cuda_fp16.h>
#include <cstdint>

#define NN   100000
#define DD   128
#define EE   800000
#define NET  2
#define TM   128
#define LN_EPS 1e-5f

#define XS 136          // fp16 row stride (272B -> conflict-free ldmatrix)

// ---- smem byte offsets (transform): 114,176 B -> 2 CTAs/SM ----
#define OFF_XH 0            // feat hi (fp16)
#define OFF_B0 34816        // WcK, then K stage
#define OFF_B1 69632        // WcQ, then WcV
#define OFF_SC 104448       // 128*16 fp32 = 8KB
#define OFF_BI 112640       // 384 fp32 = 1536B
#define SMEM_BYTES 114176

// ---- scratch (device globals) ----
__device__ __nv_bfloat16 g_Whb[(size_t)NET * NN * DD];   // bf16 messages
__device__ __half g_Wc[NET * 3 * DD * DD];               // composite fp16 weights
__device__ float g_bias[NET * 3 * DD];                   // composite biases
__device__ int g_cnt[NET * NN];
__device__ int g_off[NET * NN + 1];
__device__ int g_cur[NET * NN];
__device__ int g_bsum[256];
__device__ int g_sorted[NET * EE];

// ---- warp MMA primitives ----
__device__ __forceinline__ void ldmat4(uint32_t* r, uint32_t addr) {
    asm volatile("ldmatrix.sync.aligned.m8n8.x4.shared.b16 {%0,%1,%2,%3}, [%4];"
        : "=r"(r[0]), "=r"(r[1]), "=r"(r[2]), "=r"(r[3]) : "r"(addr));
}
__device__ __forceinline__ void ldmat4t(uint32_t* r, uint32_t addr) {
    asm volatile("ldmatrix.sync.aligned.m8n8.x4.trans.shared.b16 {%0,%1,%2,%3}, [%4];"
        : "=r"(r[0]), "=r"(r[1]), "=r"(r[2]), "=r"(r[3]) : "r"(addr));
}
__device__ __forceinline__ void mma16816(float* c, const uint32_t* a, const uint32_t* b) {
    asm volatile("mma.sync.aligned.m16n8k16.row.col.f32.f16.f16.f32 "
        "{%0,%1,%2,%3}, {%4,%5,%6,%7}, {%8,%9}, {%0,%1,%2,%3};"
        : "+f"(c[0]), "+f"(c[1]), "+f"(c[2]), "+f"(c[3])
        : "r"(a[0]), "r"(a[1]), "r"(a[2]), "r"(a[3]), "r"(b[0]), "r"(b[1]));
}
#define CP_COMMIT() asm volatile("cp.async.commit_group;" ::: "memory")
#define CP_WAIT(n)  asm volatile("cp.async.wait_group %0;" :: "n"(n) : "memory")

__device__ __forceinline__ void cpw(uint32_t sb, int offW, const __half* __restrict__ gsrc, int t) {
#pragma unroll
    for (int i = 0; i < 8; i++) {
        int u = i * 256 + t;
        int k = u >> 4, n16 = u & 15;
        uint32_t dh = sb + offW + k * (XS * 2) + n16 * 16;
        const char* gh = (const char*)gsrc + k * 256 + n16 * 16;
        asm volatile("cp.async.cg.shared.global [%0], [%1], 16;" :: "r"(dh), "l"(gh));
    }
}

// fp16 GEMM, warp tile M16 x N128, hi-only
__device__ __forceinline__ void wgemm(char* smem, float acc[16][4], int offW, int w, int lane) {
    const int r = lane & 7, sel = lane >> 3;
    const int rowoff = (sel & 1) ? 8 : 0;
    const int coloff = (sel & 2) ? 8 : 0;
    const uint32_t sb = (uint32_t)__cvta_generic_to_shared(smem);
    const int arow = 16 * w + r + rowoff;
    const uint32_t axh = sb + OFF_XH + (uint32_t)(arow * XS + coloff) * 2;
#pragma unroll
    for (int kk = 0; kk < 8; kk++) {
        uint32_t Ah[4];
        ldmat4(Ah, axh + kk * 32);
        const int brow = kk * 16 + r + rowoff;
        const uint32_t bh = sb + offW + (uint32_t)(brow * XS + coloff) * 2;
#pragma unroll
        for (int nt16 = 0; nt16 < 8; nt16++) {
            uint32_t Bh[4];
            ldmat4t(Bh, bh + nt16 * 32);
            mma16816(acc[2 * nt16],     Ah, Bh);
            mma16816(acc[2 * nt16 + 1], Ah, Bh + 2);
        }
    }
}

__device__ __forceinline__ void zacc(float acc[16][4]) {
#pragma unroll
    for (int i = 0; i < 16; i++) { acc[i][0] = acc[i][1] = acc[i][2] = acc[i][3] = 0.f; }
}

// ---- composite weight prep (fused bias): Wc[mat] = Wt @ {K,Q,V}w ; bias = bt@W + b ----
__global__ void __launch_bounds__(256) wprep_kernel(
    const float* __restrict__ Wt, const float* __restrict__ bt,
    const float* __restrict__ Kw, const float* __restrict__ Kb,
    const float* __restrict__ Qw, const float* __restrict__ Qb,
    const float* __restrict__ Vw, const float* __restrict__ Vb)
{
    int q = blockIdx.x & 3, mat = blockIdx.x >> 2;
    int e = blockIdx.y;
    const float* srcs[3] = {Kw, Qw, Vw};
    const float* bsrc[3] = {Kb, Qb, Vb};
    const float* A = Wt + (size_t)e * 16384;
    const float* B = srcs[mat] + (size_t)e * 16384;
    extern __shared__ float s[];
    float* sA = s;
    float* sB = s + 16384;
    int t = threadIdx.x;
    for (int i = t; i < 4096; i += 256) ((float4*)sA)[i] = ((const float4*)A)[i];
    for (int i = t; i < 1024; i += 256) {
        int j = i >> 3, cc = (i & 7) * 4;
        *(float4*)(sB + j * 32 + cc) = *(const float4*)(B + (size_t)j * 128 + q * 32 + cc);
    }
    __syncthreads();
    int r0 = (t >> 2) * 2, c0 = (t & 3) * 8;
    float acc0[8] = {0,0,0,0,0,0,0,0}, acc1[8] = {0,0,0,0,0,0,0,0};
    for (int j = 0; j < 128; j++) {
        float a0 = sA[r0 * 128 + j], a1 = sA[(r0 + 1) * 128 + j];
        float4 b0 = *(float4*)(sB + j * 32 + c0);
        float4 b1 = *(float4*)(sB + j * 32 + c0 + 4);
        acc0[0] += a0 * b0.x; acc0[1] += a0 * b0.y; acc0[2] += a0 * b0.z; acc0[3] += a0 * b0.w;
        acc0[4] += a0 * b1.x; acc0[5] += a0 * b1.y; acc0[6] += a0 * b1.z; acc0[7] += a0 * b1.w;
        acc1[0] += a1 * b0.x; acc1[1] += a1 * b0.y; acc1[2] += a1 * b0.z; acc1[3] += a1 * b0.w;
        acc1[4] += a1 * b1.x; acc1[5] += a1 * b1.y; acc1[6] += a1 * b1.z; acc1[7] += a1 * b1.w;
    }
    __half* C = g_Wc + (size_t)(e * 3 + mat) * 16384;
#pragma unroll
    for (int cc = 0; cc < 8; cc += 2) {
        __half2 p0 = __floats2half2_rn(acc0[cc], acc0[cc + 1]);
        __half2 p1 = __floats2half2_rn(acc1[cc], acc1[cc + 1]);
        *(uint32_t*)(C + (size_t)r0 * 128 + q * 32 + c0 + cc) = *(uint32_t*)&p0;
        *(uint32_t*)(C + (size_t)(r0 + 1) * 128 + q * 32 + c0 + cc) = *(uint32_t*)&p1;
    }
    // fused composite bias for this block's 32 columns
    if (t < 32) {
        int col = q * 32 + t;
        float sv = bsrc[mat][e * 128 + col];
        for (int j = 0; j < 128; j++) sv += bt[e * 128 + j] * sB[j * 32 + t];
        g_bias[(e * 3 + mat) * 128 + col] = sv;
    }
}

// ================= fused transform: K,Q,V from feat (2 CTAs/SM) =================
__global__ void __launch_bounds__(256, 2) transform_kernel(const float* __restrict__ feat)
{
    extern __shared__ char smem[];
    const uint32_t sb = (uint32_t)__cvta_generic_to_shared(smem);
    const int e    = blockIdx.y;
    const int base = blockIdx.x * TM;
    const int t    = threadIdx.x;
    const int w = t >> 5, lane = t & 31;
    const int g = lane >> 2, c = lane & 3;
    const int R0 = 16 * w + g, R1 = R0 + 8;
    float* sScf = (float*)(smem + OFF_SC);
    float* sBI  = (float*)(smem + OFF_BI);
    const __half* Wb = g_Wc + (size_t)e * 3 * 16384;

    cpw(sb, OFF_B0, Wb,         t); CP_COMMIT();   // WcK
    cpw(sb, OFF_B1, Wb + 16384, t); CP_COMMIT();   // WcQ

    if (t < 128) {
        sBI[t]       = g_bias[(e * 3 + 0) * 128 + t];
        sBI[128 + t] = g_bias[(e * 3 + 1) * 128 + t];
        sBI[256 + t] = g_bias[(e * 3 + 2) * 128 + t];
    }

    // feat -> XH (fp16 hi only)
#pragma unroll
    for (int i = 0; i < 16; i++) {
        int u = i * 256 + t;
        int m = u >> 5, k = (u & 31) * 4;
        int node = base + m;
        float4 v = make_float4(0.f, 0.f, 0.f, 0.f);
        if (node < NN) v = *(const float4*)(feat + (size_t)node * DD + k);
        __half2 h0 = __floats2half2_rn(v.x, v.y);
        __half2 h1 = __floats2half2_rn(v.z, v.w);
        uint2 hv;
        hv.x = *(uint32_t*)&h0; hv.y = *(uint32_t*)&h1;
        *(uint2*)(smem + OFF_XH + ((size_t)m * XS + k) * 2) = hv;
    }
    CP_WAIT(1);                                    // WcK ready
    __syncthreads();

    float acc[16][4];

    // ---- GEMM K ----
    zacc(acc);
    wgemm(smem, acc, OFF_B0, w, lane);
    __syncthreads();                               // B0 reads done

    // stage K (+bK) -> B0 (overwrite WcK)
#pragma unroll
    for (int nt = 0; nt < 16; nt++) {
        int col = nt * 8 + 2 * c;
        float bx = sBI[col], by = sBI[col + 1];
        __half2 p0 = __floats2half2_rn(acc[nt][0] + bx, acc[nt][1] + by);
        __half2 p1 = __floats2half2_rn(acc[nt][2] + bx, acc[nt][3] + by);
        *(uint32_t*)(smem + OFF_B0 + ((size_t)R0 * XS + col) * 2) = *(uint32_t*)&p0;
        *(uint32_t*)(smem + OFF_B0 + ((size_t)R1 * XS + col) * 2) = *(uint32_t*)&p1;
    }
    CP_WAIT(0);                                    // WcQ ready
    __syncthreads();                               // K staged + WcQ visible

    // ---- GEMM Q ----
    zacc(acc);
    wgemm(smem, acc, OFF_B1, w, lane);
    __syncthreads();                               // B1 reads done -> can overwrite
    cpw(sb, OFF_B1, Wb + 2 * 16384, t); CP_COMMIT();   // WcV (overlaps scores+softmax)

#pragma unroll
    for (int nt = 0; nt < 16; nt++) {
        int col = nt * 8 + 2 * c;
        float bx = sBI[128 + col], by = sBI[128 + col + 1];
        acc[nt][0] += bx; acc[nt][1] += by;
        acc[nt][2] += bx; acc[nt][3] += by;
    }

    // ---- scores (K from fp16 B0) ----
    const float scale = 0.17677669529663687f;
#pragma unroll
    for (int gp = 0; gp < 4; gp++) {
        float2 kv0[4], kv1[4];
#pragma unroll
        for (int j = 0; j < 4; j++) {
            __half2 k0 = *(const __half2*)(smem + OFF_B0 + ((size_t)R0 * XS + gp * 32 + j * 8 + 2 * c) * 2);
            __half2 k1 = *(const __half2*)(smem + OFF_B0 + ((size_t)R1 * XS + gp * 32 + j * 8 + 2 * c) * 2);
            kv0[j] = __half22float2(k0);
            kv1[j] = __half22float2(k1);
        }
#pragma unroll
        for (int h = 0; h < 4; h++) {
            float p0 = 0.f, p1 = 0.f;
#pragma unroll
            for (int j = 0; j < 4; j++) {
                p0 += acc[4 * h + j][0] * kv0[j].x + acc[4 * h + j][1] * kv0[j].y;
                p1 += acc[4 * h + j][2] * kv1[j].x + acc[4 * h + j][3] * kv1[j].y;
            }
            p0 += __shfl_xor_sync(0xffffffffu, p0, 1);
            p0 += __shfl_xor_sync(0xffffffffu, p0, 2);
            p1 += __shfl_xor_sync(0xffffffffu, p1, 1);
            p1 += __shfl_xor_sync(0xffffffffu, p1, 2);
            if (c == 0) {
                sScf[R0 * 16 + h * 4 + gp] = p0 * scale;
                sScf[R1 * 16 + h * 4 + gp] = p1 * scale;
            }
        }
    }
    __syncthreads();

    // ---- softmax ----
#pragma unroll
    for (int i = 0; i < 2; i++) {
        int p = t * 2 + i;
        int row = p >> 2, h = p & 3;
        float4 s = *(float4*)(sScf + row * 16 + h * 4);
        float m = fmaxf(fmaxf(s.x, s.y), fmaxf(s.z, s.w));
        float e0 = __expf(s.x - m), e1 = __expf(s.y - m), e2 = __expf(s.z - m), e3 = __expf(s.w - m);
        float inv = 1.f / (e0 + e1 + e2 + e3);
        *(float4*)(sScf + row * 16 + h * 4) = make_float4(e0 * inv, e1 * inv, e2 * inv, e3 * inv);
    }
    CP_WAIT(0);                                    // WcV ready
    __syncthreads();

    // ---- GEMM V (hi-only) ----
    zacc(acc);
    wgemm(smem, acc, OFF_B1, w, lane);
#pragma unroll
    for (int nt = 0; nt < 16; nt++) {
        int col = nt * 8 + 2 * c;
        float bx = sBI[256 + col], by = sBI[256 + col + 1];
        acc[nt][0] += bx; acc[nt][1] += by;
        acc[nt][2] += bx; acc[nt][3] += by;
    }

    // ---- combine -> g_Whb (bf16) ----
    const int n0 = base + R0, n1 = base + R1;
    __nv_bfloat16* op0 = g_Whb + ((size_t)e * NN + n0) * DD;
    __nv_bfloat16* op1 = g_Whb + ((size_t)e * NN + n1) * DD;
#pragma unroll
    for (int h = 0; h < 4; h++) {
        float4 a0 = *(float4*)(sScf + R0 * 16 + 4 * h);
        float4 a1 = *(float4*)(sScf + R1 * 16 + 4 * h);
#pragma unroll
        for (int j3 = 0; j3 < 4; j3++) {
            int col = (h * 4 + j3) * 8 + 2 * c;
            float o00 = a0.x * acc[j3][0]      + a0.y * acc[4 + j3][0]
                      + a0.z * acc[8 + j3][0]  + a0.w * acc[12 + j3][0];
            float o01 = a0.x * acc[j3][1]      + a0.y * acc[4 + j3][1]
                      + a0.z * acc[8 + j3][1]  + a0.w * acc[12 + j3][1];
            float o10 = a1.x * acc[j3][2]      + a1.y * acc[4 + j3][2]
                      + a1.z * acc[8 + j3][2]  + a1.w * acc[12 + j3][2];
            float o11 = a1.x * acc[j3][3]      + a1.y * acc[4 + j3][3]
                      + a1.z * acc[8 + j3][3]  + a1.w * acc[12 + j3][3];
            if (n0 < NN) {
                __nv_bfloat162 pk = __floats2bfloat162_rn(o00, o01);
                *(uint32_t*)(op0 + col) = *(uint32_t*)&pk;
            }
            if (n1 < NN) {
                __nv_bfloat162 pk = __floats2bfloat162_rn(o10, o11);
                *(uint32_t*)(op1 + col) = *(uint32_t*)&pk;
            }
        }
    }
}

// ================= CSR build =================
__global__ void cnt_zero_kernel() {
    int i = blockIdx.x * 1024 + threadIdx.x;
    if (i < NET * NN) g_cnt[i] = 0;
}
__global__ void cnt_kernel(const int* __restrict__ dst) {
    int e = blockIdx.y;
    int i = blockIdx.x * blockDim.x + threadIdx.x;
    if (i < EE) atomicAdd(&g_cnt[e * NN + dst[(size_t)e * EE + i]], 1);
}
__global__ void scan_a_kernel() {
    __shared__ int wsum[32];
    int t = threadIdx.x, lane = t & 31, wid = t >> 5;
    int gid = blockIdx.x * 1024 + t;
    int v = (gid < NET * NN) ? g_cnt[gid] : 0;
    int x = v;
#pragma unroll
    for (int o = 1; o < 32; o <<= 1) { int y = __shfl_up_sync(0xffffffffu, x, o); if (lane >= o) x += y; }
    if (lane == 31) wsum[wid] = x;
    __syncthreads();
    if (wid == 0) {
        int s = wsum[lane];
#pragma unroll
        for (int o = 1; o < 32; o <<= 1) { int y = __shfl_up_sync(0xffffffffu, s, o); if (lane >= o) s += y; }
        wsum[lane] = s;
    }
    __syncthreads();
    int pfx = wid ? wsum[wid - 1] : 0;
    if (gid < NET * NN) g_off[gid] = pfx + x - v;
    if (t == 1023) g_bsum[blockIdx.x] = pfx + x;
}
__global__ void scan_b_kernel() {
    __shared__ int wsum[8];
    int t = threadIdx.x, lane = t & 31, wid = t >> 5;
    int v = (t < 196) ? g_bsum[t] : 0;
    int x = v;
#pragma unroll
    for (int o = 1; o < 32; o <<= 1) { int y = __shfl_up_sync(0xffffffffu, x, o); if (lane >= o) x += y; }
    if (lane == 31) wsum[wid] = x;
    __syncthreads();
    if (t == 0) {
        int run = 0;
#pragma unroll
        for (int i = 0; i < 8; i++) { int tmp = wsum[i]; wsum[i] = run; run += tmp; }
    }
    __syncthreads();
    if (t < 196) g_bsum[t] = wsum[wid] + x - v;
}
__global__ void scan_c_kernel() {
    int gid = blockIdx.x * 1024 + threadIdx.x;
    if (gid < NET * NN) {
        int o = g_off[gid] + g_bsum[gid >> 10];
        g_off[gid] = o;
        g_cur[gid] = o;
    }
    if (gid == 0) g_off[NET * NN] = NET * EE;
}
__global__ void fill_kernel(const int* __restrict__ src, const int* __restrict__ dst) {
    int e = blockIdx.y;
    int i = blockIdx.x * blockDim.x + threadIdx.x;
    if (i < EE) {
        int d = dst[(size_t)e * EE + i];
        int pos = atomicAdd(&g_cur[e * NN + d], 1);
        g_sorted[pos] = src[(size_t)e * EE + i];
    }
}

// ================= fused gather (bf16, 8-wide MLP) + mean + residual + LayerNorm =================
__global__ void gather_ln_kernel(const float* __restrict__ feat,
                                 const float* __restrict__ ln_g, const float* __restrict__ ln_b,
                                 float* __restrict__ out) {
    int w    = (blockIdx.x * blockDim.x + threadIdx.x) >> 5;
    int lane = threadIdx.x & 31;
    if (w >= NN) return;
    float a0 = 0.f, a1 = 0.f, a2 = 0.f, a3 = 0.f;
#pragma unroll
    for (int e = 0; e < NET; e++) {
        int beg = g_off[e * NN + w], end = g_off[e * NN + w + 1];
        const __nv_bfloat16* WhE = g_Whb + (size_t)e * NN * DD + lane * 4;
        float t0 = 0.f, t1 = 0.f, t2 = 0.f, t3 = 0.f;
        int i = beg;
        for (; i + 8 <= end; i += 8) {
            int sx[8];
#pragma unroll
            for (int u = 0; u < 8; u++) sx[u] = __ldg(&g_sorted[i + u]);
            uint2 uu[8];
#pragma unroll
            for (int u = 0; u < 8; u++) uu[u] = *(const uint2*)(WhE + (size_t)sx[u] * DD);
#pragma unroll
            for (int u = 0; u < 8; u++) {
                float2 p0 = __bfloat1622float2(*(__nv_bfloat162*)&uu[u].x);
                float2 p1 = __bfloat1622float2(*(__nv_bfloat162*)&uu[u].y);
                t0 += p0.x; t1 += p0.y; t2 += p1.x; t3 += p1.y;
            }
        }
        for (; i + 2 <= end; i += 2) {
            int s0 = __ldg(&g_sorted[i]), s1 = __ldg(&g_sorted[i + 1]);
            uint2 u0 = *(const uint2*)(WhE + (size_t)s0 * DD);
            uint2 u1 = *(const uint2*)(WhE + (size_t)s1 * DD);
            float2 p0 = __bfloat1622float2(*(__nv_bfloat162*)&u0.x);
            float2 p1 = __bfloat1622float2(*(__nv_bfloat162*)&u0.y);
            float2 q0 = __bfloat1622float2(*(__nv_bfloat162*)&u1.x);
            float2 q1 = __bfloat1622float2(*(__nv_bfloat162*)&u1.y);
            t0 += p0.x + q0.x; t1 += p0.y + q0.y;
            t2 += p1.x + q1.x; t3 += p1.y + q1.y;
        }
        if (i < end) {
            int s0 = __ldg(&g_sorted[i]);
            uint2 u0 = *(const uint2*)(WhE + (size_t)s0 * DD);
            float2 p0 = __bfloat1622float2(*(__nv_bfloat162*)&u0.x);
            float2 p1 = __bfloat1622float2(*(__nv_bfloat162*)&u0.y);
            t0 += p0.x; t1 += p0.y; t2 += p1.x; t3 += p1.y;
        }
        float inv = 1.f / fmaxf((float)(end - beg), 1.f);
        a0 += t0 * inv; a1 += t1 * inv; a2 += t2 * inv; a3 += t3 * inv;
    }
    float4 f = ((const float4*)(feat + (size_t)w * DD))[lane];
    float4 h = make_float4(a0 + f.x, a1 + f.y, a2 + f.z, a3 + f.w);

    float s = h.x + h.y + h.z + h.w;
#pragma unroll
    for (int o = 16; o; o >>= 1) s += __shfl_xor_sync(0xffffffffu, s, o);
    float mu = s * (1.0f / 128.0f);

    float dx = h.x - mu, dy = h.y - mu, dz = h.z - mu, dw = h.w - mu;
    float q = dx * dx + dy * dy + dz * dz + dw * dw;
#pragma unroll
    for (int o = 16; o; o >>= 1) q += __shfl_xor_sync(0xffffffffu, q, o);
    float inv = rsqrtf(q * (1.0f / 128.0f) + LN_EPS);

    float4 gg = ((const float4*)ln_g)[lane];
    float4 bb = ((const float4*)ln_b)[lane];
    float4 o4 = make_float4(dx * inv * gg.x + bb.x, dy * inv * gg.y + bb.y,
                            dz * inv * gg.z + bb.z, dw * inv * gg.w + bb.w);
    ((float4*)out)[(size_t)w * 32 + lane] = o4;
}

extern "C" void kernel_launch(void* const* d_in, const int* in_sizes, int n_in,
                              void* d_out, int out_size) {
    const float* feat = (const float*)d_in[0];
    const int*   src  = (const int*)d_in[1];
    const int*   dst  = (const int*)d_in[2];
    const float* Wt   = (const float*)d_in[3];
    const float* bt   = (const float*)d_in[4];
    const float* Kw   = (const float*)d_in[5];
    const float* Kb   = (const float*)d_in[6];
    const float* Qw   = (const float*)d_in[7];
    const float* Qb   = (const float*)d_in[8];
    const float* Vw   = (const float*)d_in[9];
    const float* Vb   = (const float*)d_in[10];
    const float* ln_g = (const float*)d_in[11];
    const float* ln_b = (const float*)d_in[12];
    float* out = (float*)d_out;

    cudaFuncSetAttribute(transform_kernel, cudaFuncAttributeMaxDynamicSharedMemorySize, SMEM_BYTES);
    cudaFuncSetAttribute(wprep_kernel, cudaFuncAttributeMaxDynamicSharedMemorySize, 81920);

    // Streams/events created ONCE on the first (non-captured) call; reused during
    // capture so the capture call is allocation-free (R11 audit failure fix).
    static cudaStream_t sA = nullptr, sB = nullptr;
    static cudaEvent_t evF = nullptr, evA = nullptr, evB = nullptr;
    if (sA == nullptr) {
        cudaStreamCreateWithFlags(&sA, cudaStreamNonBlocking);
        cudaStreamCreateWithFlags(&sB, cudaStreamNonBlocking);
        cudaEventCreateWithFlags(&evF, cudaEventDisableTiming);
        cudaEventCreateWithFlags(&evA, cudaEventDisableTiming);
        cudaEventCreateWithFlags(&evB, cudaEventDisableTiming);
        cnt_zero_kernel<<<1, 32, 0, sA>>>();   // materialize stream pools now
        cnt_zero_kernel<<<1, 32, 0, sB>>>();
    }

    cudaEventRecord(evF, 0);
    cudaStreamWaitEvent(sA, evF, 0);
    cudaStreamWaitEvent(sB, evF, 0);

    // Branch A: CSR build (depends only on src/dst)
    cnt_zero_kernel<<<196, 1024, 0, sA>>>();
    cnt_kernel<<<dim3(EE / 256, NET), 256, 0, sA>>>(dst);
    scan_a_kernel<<<196, 1024, 0, sA>>>();
    scan_b_kernel<<<1, 256, 0, sA>>>();
    scan_c_kernel<<<196, 1024, 0, sA>>>();
    fill_kernel<<<dim3(EE / 256, NET), 256, 0, sA>>>(src, dst);
    cudaEventRecord(evA, sA);

    // Branch B: weight prep (fused bias) + transform
    wprep_kernel<<<dim3(12, NET), 256, 81920, sB>>>(Wt, bt, Kw, Kb, Qw, Qb, Vw, Vb);
    transform_kernel<<<dim3((NN + TM - 1) / TM, NET), 256, SMEM_BYTES, sB>>>(feat);
    cudaEventRecord(evB, sB);

    // Join, then final gather + LayerNorm on the base stream
    cudaStreamWaitEvent(0, evA, 0);
    cudaStreamWaitEvent(0, evB, 0);
    gather_ln_kernel<<<(NN * 32 + 255) / 256, 256>>>(feat, ln_g, ln_b, out);
}